// round 1
// baseline (speedup 1.0000x reference)
#include <cuda_runtime.h>
#include <math.h>

#define BB 8
#define NNODE 256
#define FF 512
#define HH 256
#define MM (BB*NNODE)        // 2048 rows for all GEMMs
#define NMAT (NNODE*NNODE)   // 65536
#define OUT_MAT (BB*NMAT)    // 524288

// ---------------- scratch (device globals; no allocation allowed) ----------------
__device__ float g_t1[MM*HH];
__device__ float g_imgh[MM*HH];
__device__ float g_txth[MM*HH];
__device__ float g_a[MM*HH];
__device__ float g_c[MM*HH];
__device__ float g_partial[2*256];

// ---------------- generic fused GEMM: C = act(A[M,K] @ W[K,N] + bias) ----------------
// 64x64 block tile, 256 threads, 4x4 register tile, K staged in 16-chunks.
__global__ __launch_bounds__(256) void gemm_bias_act(
    const float* __restrict__ A, const float* __restrict__ W,
    const float* __restrict__ bias, float* __restrict__ C,
    int K, int N, int do_relu)
{
    __shared__ float As[16][64];   // k-major
    __shared__ float Ws[16][64];   // k-major
    const int tid = threadIdx.x;
    const int tx = tid & 15, ty = tid >> 4;
    const int bm = blockIdx.x << 6, bn = blockIdx.y << 6;
    const int lr = tid >> 2;            // 0..63 row in A tile
    const int lk = (tid & 3) << 2;      // 0,4,8,12
    const int kr = ty;                  // 0..15 row in W tile
    const int nc = tx << 2;             // 0..60
    float acc[4][4] = {};

    for (int k0 = 0; k0 < K; k0 += 16) {
        float4 av = *reinterpret_cast<const float4*>(A + (size_t)(bm + lr) * K + k0 + lk);
        float4 wv = *reinterpret_cast<const float4*>(W + (size_t)(k0 + kr) * N + bn + nc);
        __syncthreads();
        As[lk+0][lr] = av.x; As[lk+1][lr] = av.y; As[lk+2][lr] = av.z; As[lk+3][lr] = av.w;
        *reinterpret_cast<float4*>(&Ws[kr][nc]) = wv;
        __syncthreads();
        #pragma unroll
        for (int k = 0; k < 16; ++k) {
            float4 af = *reinterpret_cast<const float4*>(&As[k][ty << 2]);
            float4 wf = *reinterpret_cast<const float4*>(&Ws[k][tx << 2]);
            float ar[4] = {af.x, af.y, af.z, af.w};
            float wr[4] = {wf.x, wf.y, wf.z, wf.w};
            #pragma unroll
            for (int i = 0; i < 4; ++i)
                #pragma unroll
                for (int j = 0; j < 4; ++j)
                    acc[i][j] = fmaf(ar[i], wr[j], acc[i][j]);
        }
    }

    float bv[4] = {0.f, 0.f, 0.f, 0.f};
    if (bias) {
        float4 bb = *reinterpret_cast<const float4*>(bias + bn + (tx << 2));
        bv[0] = bb.x; bv[1] = bb.y; bv[2] = bb.z; bv[3] = bb.w;
    }
    #pragma unroll
    for (int i = 0; i < 4; ++i) {
        float v0 = acc[i][0] + bv[0];
        float v1 = acc[i][1] + bv[1];
        float v2 = acc[i][2] + bv[2];
        float v3 = acc[i][3] + bv[3];
        if (do_relu) {
            v0 = fmaxf(v0, 0.f); v1 = fmaxf(v1, 0.f);
            v2 = fmaxf(v2, 0.f); v3 = fmaxf(v3, 0.f);
        }
        float4 o; o.x = v0; o.y = v1; o.z = v2; o.w = v3;
        *reinterpret_cast<float4*>(C + (size_t)(bm + (ty << 2) + i) * N + bn + (tx << 2)) = o;
    }
}

// ---------------- pairwise: out[b,i,j] = sigmoid( sum_h relu(a[b,i,h]+c[b,j,h]) * w2[h] + b2 ) ----
// b1 is pre-folded into a (bias of the a-projection GEMM).
__global__ __launch_bounds__(256) void pair_scores_kernel(
    const float* __restrict__ Aa, const float* __restrict__ Cc,
    const float* __restrict__ w2, const float* __restrict__ b2p,
    float* __restrict__ out)
{
    __shared__ float aS[32][64];   // h-major
    __shared__ float cS[32][64];   // h-major
    __shared__ float w2s[HH];
    const int tid = threadIdx.x;
    const int tx = tid & 15, ty = tid >> 4;
    const int i0 = blockIdx.x << 6, j0 = blockIdx.y << 6;
    const int b  = blockIdx.z;
    w2s[tid] = w2[tid];                  // blockDim == HH == 256
    const int lr = tid >> 2;             // 0..63
    const int lk = (tid & 3) << 3;       // 0,8,16,24
    const float* Ab = Aa + (size_t)b * NNODE * HH;
    const float* Cb = Cc + (size_t)b * NNODE * HH;
    float acc[4][4] = {};

    for (int h0 = 0; h0 < HH; h0 += 32) {
        const float* ap = Ab + (size_t)(i0 + lr) * HH + h0 + lk;
        const float* cp = Cb + (size_t)(j0 + lr) * HH + h0 + lk;
        float4 av0 = *reinterpret_cast<const float4*>(ap);
        float4 av1 = *reinterpret_cast<const float4*>(ap + 4);
        float4 cv0 = *reinterpret_cast<const float4*>(cp);
        float4 cv1 = *reinterpret_cast<const float4*>(cp + 4);
        __syncthreads();
        aS[lk+0][lr]=av0.x; aS[lk+1][lr]=av0.y; aS[lk+2][lr]=av0.z; aS[lk+3][lr]=av0.w;
        aS[lk+4][lr]=av1.x; aS[lk+5][lr]=av1.y; aS[lk+6][lr]=av1.z; aS[lk+7][lr]=av1.w;
        cS[lk+0][lr]=cv0.x; cS[lk+1][lr]=cv0.y; cS[lk+2][lr]=cv0.z; cS[lk+3][lr]=cv0.w;
        cS[lk+4][lr]=cv1.x; cS[lk+5][lr]=cv1.y; cS[lk+6][lr]=cv1.z; cS[lk+7][lr]=cv1.w;
        __syncthreads();
        #pragma unroll
        for (int h = 0; h < 32; ++h) {
            float w = w2s[h0 + h];
            float4 af = *reinterpret_cast<const float4*>(&aS[h][ty << 2]);
            float4 cf = *reinterpret_cast<const float4*>(&cS[h][tx << 2]);
            float ar[4] = {af.x, af.y, af.z, af.w};
            float cr[4] = {cf.x, cf.y, cf.z, cf.w};
            #pragma unroll
            for (int i = 0; i < 4; ++i)
                #pragma unroll
                for (int j = 0; j < 4; ++j)
                    acc[i][j] = fmaf(fmaxf(ar[i] + cr[j], 0.f), w, acc[i][j]);
        }
    }

    const float b2 = b2p[0];
    #pragma unroll
    for (int i = 0; i < 4; ++i) {
        float s0 = acc[i][0] + b2, s1 = acc[i][1] + b2;
        float s2 = acc[i][2] + b2, s3 = acc[i][3] + b2;
        float4 o;
        o.x = 1.f / (1.f + __expf(-s0));
        o.y = 1.f / (1.f + __expf(-s1));
        o.z = 1.f / (1.f + __expf(-s2));
        o.w = 1.f / (1.f + __expf(-s3));
        *reinterpret_cast<float4*>(out + ((size_t)b * NNODE + i0 + (ty << 2) + i) * NNODE
                                       + j0 + (tx << 2)) = o;
    }
}

// ---------------- invariance reduction (deterministic two-stage tree) ----------------
__global__ __launch_bounds__(256) void reduce_stage1(const float* __restrict__ causal)
{
    const int p = blockIdx.x * 256 + threadIdx.x;   // 0..65535 (i,j) pair
    float x[8];
    #pragma unroll
    for (int b = 0; b < 8; ++b) x[b] = causal[b * NMAT + p];
    float stab = 0.f, s = 0.f;
    #pragma unroll
    for (int b = 0; b < 8; ++b) { stab += fabsf(x[b] - x[(b + 7) & 7]); s += x[b]; }
    const float m = s * 0.125f;
    float var = 0.f;
    #pragma unroll
    for (int b = 0; b < 8; ++b) { float d = x[b] - m; var = fmaf(d, d, var); }
    float sd = sqrtf(var * (1.f / 7.f));   // ddof=1

    #pragma unroll
    for (int o = 16; o; o >>= 1) {
        stab += __shfl_down_sync(0xffffffffu, stab, o);
        sd   += __shfl_down_sync(0xffffffffu, sd, o);
    }
    __shared__ float sm[8][2];
    const int wid = threadIdx.x >> 5, lane = threadIdx.x & 31;
    if (lane == 0) { sm[wid][0] = stab; sm[wid][1] = sd; }
    __syncthreads();
    if (threadIdx.x == 0) {
        float a = 0.f, c = 0.f;
        #pragma unroll
        for (int w = 0; w < 8; ++w) { a += sm[w][0]; c += sm[w][1]; }
        g_partial[blockIdx.x * 2 + 0] = a;
        g_partial[blockIdx.x * 2 + 1] = c;
    }
}

__global__ __launch_bounds__(256) void reduce_stage2(float* __restrict__ inv)
{
    float a = g_partial[threadIdx.x * 2 + 0];
    float c = g_partial[threadIdx.x * 2 + 1];
    #pragma unroll
    for (int o = 16; o; o >>= 1) {
        a += __shfl_down_sync(0xffffffffu, a, o);
        c += __shfl_down_sync(0xffffffffu, c, o);
    }
    __shared__ float sm[8][2];
    const int wid = threadIdx.x >> 5, lane = threadIdx.x & 31;
    if (lane == 0) { sm[wid][0] = a; sm[wid][1] = c; }
    __syncthreads();
    if (threadIdx.x == 0) {
        float sa = 0.f, sc = 0.f;
        #pragma unroll
        for (int w = 0; w < 8; ++w) { sa += sm[w][0]; sc += sm[w][1]; }
        const float stability   = sa / (8.f * 65536.f);
        const float consistency = sc / 65536.f;
        inv[0] = 1.f - (stability + consistency) * 0.5f;
    }
}

// ---------------- launch ----------------
extern "C" void kernel_launch(void* const* d_in, const int* in_sizes, int n_in,
                              void* d_out, int out_size)
{
    const float* img    = (const float*)d_in[0];
    const float* txt    = (const float*)d_in[1];
    const float* ft_W1  = (const float*)d_in[2];
    const float* ft_b1  = (const float*)d_in[3];
    const float* ft_W2  = (const float*)d_in[4];
    const float* ft_b2  = (const float*)d_in[5];
    const float* sl_W1a = (const float*)d_in[6];
    const float* sl_W1b = (const float*)d_in[7];
    const float* sl_b1  = (const float*)d_in[8];
    const float* sl_W2  = (const float*)d_in[9];
    const float* sl_b2  = (const float*)d_in[10];
    const float* cn_W1a = (const float*)d_in[11];
    const float* cn_W1b = (const float*)d_in[12];
    const float* cn_b1  = (const float*)d_in[13];
    const float* cn_W2  = (const float*)d_in[14];
    const float* cn_b2  = (const float*)d_in[15];

    float* outp      = (float*)d_out;
    float* structure = outp;
    float* causal    = outp + OUT_MAT;
    float* inv       = outp + 2 * OUT_MAT;

    float *t1, *imgh, *txth, *ga, *gc;
    cudaGetSymbolAddress((void**)&t1,   g_t1);
    cudaGetSymbolAddress((void**)&imgh, g_imgh);
    cudaGetSymbolAddress((void**)&txth, g_txth);
    cudaGetSymbolAddress((void**)&ga,   g_a);
    cudaGetSymbolAddress((void**)&gc,   g_c);

    const dim3 gemm_grid(MM / 64, HH / 64);   // 32 x 4
    const dim3 pair_grid(NNODE / 64, NNODE / 64, BB); // 4 x 4 x 8

    // feature_transform (image): t1 = relu(img @ ft_W1 + ft_b1); imgh = t1 @ ft_W2 + ft_b2
    gemm_bias_act<<<gemm_grid, 256>>>(img, ft_W1, ft_b1, t1, FF, HH, 1);
    gemm_bias_act<<<gemm_grid, 256>>>(t1, ft_W2, ft_b2, imgh, HH, HH, 0);
    // feature_transform (text)
    gemm_bias_act<<<gemm_grid, 256>>>(txt, ft_W1, ft_b1, t1, FF, HH, 1);
    gemm_bias_act<<<gemm_grid, 256>>>(t1, ft_W2, ft_b2, txth, HH, HH, 0);

    // structure_learning projections (fold sl_b1 into the a-side)
    gemm_bias_act<<<gemm_grid, 256>>>(imgh, sl_W1a, sl_b1, ga, HH, HH, 0);
    gemm_bias_act<<<gemm_grid, 256>>>(txth, sl_W1b, nullptr, gc, HH, HH, 0);
    pair_scores_kernel<<<pair_grid, 256>>>(ga, gc, sl_W2, sl_b2, structure);

    // causal_net projections on structure (treated as [B,N,H])
    gemm_bias_act<<<gemm_grid, 256>>>(structure, cn_W1a, cn_b1, ga, HH, HH, 0);
    gemm_bias_act<<<gemm_grid, 256>>>(structure, cn_W1b, nullptr, gc, HH, HH, 0);
    pair_scores_kernel<<<pair_grid, 256>>>(ga, gc, cn_W2, cn_b2, causal);

    // invariance score
    reduce_stage1<<<256, 256>>>(causal);
    reduce_stage2<<<1, 256>>>(inv);
}

// round 2
// speedup vs baseline: 1.3281x; 1.3281x over previous
#include <cuda_runtime.h>
#include <math.h>

#define BB 8
#define NNODE 256
#define FF 512
#define HH 256
#define MM (BB*NNODE)        // 2048 rows per logical matrix
#define M2 (2*MM)            // 4096 rows per batched GEMM launch
#define NMAT (NNODE*NNODE)   // 65536
#define OUT_MAT (BB*NMAT)    // 524288

// ---------------- scratch (device globals; no allocation allowed) ----------------
__device__ float g_x1[M2*HH];     // stage-1 hidden (img|txt)
__device__ float g_h [M2*HH];     // imgh|txth
__device__ float g_ac[M2*HH];     // a|c projections
__device__ float g_partial[2*256];

// ---------------- batched fused GEMM ----------------
// Computes two stacked GEMMs in one launch:
//   rows [0,2048):   C = act(A0 @ W0 + b0)
//   rows [2048,4096): C = act(A1 @ W1 + b1)
// 64x64 tile, 256 threads, 4x4 reg tile, K chunked by 16, double-buffered smem.
__global__ __launch_bounds__(256) void gemm2(
    const float* __restrict__ A0, const float* __restrict__ A1,
    const float* __restrict__ W0, const float* __restrict__ W1,
    const float* __restrict__ b0, const float* __restrict__ b1,
    float* __restrict__ C, int K, int do_relu)
{
    __shared__ float As[2][16][64];   // k-major
    __shared__ float Ws[2][16][64];   // k-major

    const int tid = threadIdx.x;
    const int tx = tid & 15, ty = tid >> 4;
    const int half = gridDim.x >> 1;

    const float* A; const float* W; const float* bias;
    int row0;
    if (blockIdx.x < half) { A = A0; W = W0; bias = b0; row0 = blockIdx.x << 6; }
    else                   { A = A1; W = W1; bias = b1; row0 = (blockIdx.x - half) << 6; }
    const int bn = blockIdx.y << 6;
    const int crow0 = blockIdx.x << 6;

    const int lr = tid >> 2;            // 0..63 row in A tile
    const int lk = (tid & 3) << 2;      // 0,4,8,12
    const int kr = ty;                  // 0..15 k-row in W tile
    const int nc = tx << 2;             // 0..60

    float acc[4][4] = {};

    // prologue: chunk 0
    float4 av = *reinterpret_cast<const float4*>(A + (size_t)(row0 + lr) * K + lk);
    float4 wv = *reinterpret_cast<const float4*>(W + (size_t)kr * HH + bn + nc);
    As[0][lk+0][lr]=av.x; As[0][lk+1][lr]=av.y; As[0][lk+2][lr]=av.z; As[0][lk+3][lr]=av.w;
    *reinterpret_cast<float4*>(&Ws[0][kr][nc]) = wv;
    __syncthreads();

    int cur = 0;
    const int nk = K >> 4;
    for (int t = 1; t < nk; ++t) {
        const int k0 = t << 4;
        // prefetch next chunk into registers
        av = *reinterpret_cast<const float4*>(A + (size_t)(row0 + lr) * K + k0 + lk);
        wv = *reinterpret_cast<const float4*>(W + (size_t)(k0 + kr) * HH + bn + nc);
        // compute on current buffer
        #pragma unroll
        for (int k = 0; k < 16; ++k) {
            float4 af = *reinterpret_cast<const float4*>(&As[cur][k][ty << 2]);
            float4 wf = *reinterpret_cast<const float4*>(&Ws[cur][k][tx << 2]);
            float ar[4] = {af.x, af.y, af.z, af.w};
            float wr[4] = {wf.x, wf.y, wf.z, wf.w};
            #pragma unroll
            for (int i = 0; i < 4; ++i)
                #pragma unroll
                for (int j = 0; j < 4; ++j)
                    acc[i][j] = fmaf(ar[i], wr[j], acc[i][j]);
        }
        // stage next buffer
        const int nxt = cur ^ 1;
        As[nxt][lk+0][lr]=av.x; As[nxt][lk+1][lr]=av.y; As[nxt][lk+2][lr]=av.z; As[nxt][lk+3][lr]=av.w;
        *reinterpret_cast<float4*>(&Ws[nxt][kr][nc]) = wv;
        __syncthreads();
        cur = nxt;
    }
    // last chunk
    #pragma unroll
    for (int k = 0; k < 16; ++k) {
        float4 af = *reinterpret_cast<const float4*>(&As[cur][k][ty << 2]);
        float4 wf = *reinterpret_cast<const float4*>(&Ws[cur][k][tx << 2]);
        float ar[4] = {af.x, af.y, af.z, af.w};
        float wr[4] = {wf.x, wf.y, wf.z, wf.w};
        #pragma unroll
        for (int i = 0; i < 4; ++i)
            #pragma unroll
            for (int j = 0; j < 4; ++j)
                acc[i][j] = fmaf(ar[i], wr[j], acc[i][j]);
    }

    float bv[4] = {0.f, 0.f, 0.f, 0.f};
    if (bias) {
        float4 bb = *reinterpret_cast<const float4*>(bias + bn + nc);
        bv[0] = bb.x; bv[1] = bb.y; bv[2] = bb.z; bv[3] = bb.w;
    }
    #pragma unroll
    for (int i = 0; i < 4; ++i) {
        float v0 = acc[i][0] + bv[0];
        float v1 = acc[i][1] + bv[1];
        float v2 = acc[i][2] + bv[2];
        float v3 = acc[i][3] + bv[3];
        if (do_relu) {
            v0 = fmaxf(v0, 0.f); v1 = fmaxf(v1, 0.f);
            v2 = fmaxf(v2, 0.f); v3 = fmaxf(v3, 0.f);
        }
        float4 o; o.x = v0; o.y = v1; o.z = v2; o.w = v3;
        *reinterpret_cast<float4*>(C + (size_t)(crow0 + (ty << 2) + i) * HH + bn + nc) = o;
    }
}

// ---------------- pairwise: out[b,i,j] = sigmoid( sum_h relu(a[b,i,h]+c[b,j,h]) * w2[h] + b2 )
// b1 pre-folded into a. 64x64 (i,j) tile, double-buffered h-chunks of 32.
__global__ __launch_bounds__(256) void pair_scores_kernel(
    const float* __restrict__ Aa, const float* __restrict__ Cc,
    const float* __restrict__ w2, const float* __restrict__ b2p,
    float* __restrict__ out)
{
    __shared__ float aS[2][32][64];   // h-major
    __shared__ float cS[2][32][64];   // h-major
    __shared__ float w2s[HH];

    const int tid = threadIdx.x;
    const int tx = tid & 15, ty = tid >> 4;
    const int i0 = blockIdx.x << 6, j0 = blockIdx.y << 6;
    const int b  = blockIdx.z;
    w2s[tid] = w2[tid];

    const int lr = tid >> 2;             // 0..63
    const int lk = (tid & 3) << 3;       // 0,8,16,24
    const float* Ab = Aa + (size_t)b * NNODE * HH;
    const float* Cb = Cc + (size_t)b * NNODE * HH;
    float acc[4][4] = {};

    // prologue: chunk 0
    const float* ap = Ab + (size_t)(i0 + lr) * HH + lk;
    const float* cp = Cb + (size_t)(j0 + lr) * HH + lk;
    float4 av0 = *reinterpret_cast<const float4*>(ap);
    float4 av1 = *reinterpret_cast<const float4*>(ap + 4);
    float4 cv0 = *reinterpret_cast<const float4*>(cp);
    float4 cv1 = *reinterpret_cast<const float4*>(cp + 4);
    aS[0][lk+0][lr]=av0.x; aS[0][lk+1][lr]=av0.y; aS[0][lk+2][lr]=av0.z; aS[0][lk+3][lr]=av0.w;
    aS[0][lk+4][lr]=av1.x; aS[0][lk+5][lr]=av1.y; aS[0][lk+6][lr]=av1.z; aS[0][lk+7][lr]=av1.w;
    cS[0][lk+0][lr]=cv0.x; cS[0][lk+1][lr]=cv0.y; cS[0][lk+2][lr]=cv0.z; cS[0][lk+3][lr]=cv0.w;
    cS[0][lk+4][lr]=cv1.x; cS[0][lk+5][lr]=cv1.y; cS[0][lk+6][lr]=cv1.z; cS[0][lk+7][lr]=cv1.w;
    __syncthreads();

    int cur = 0;
    for (int t = 1; t < 8; ++t) {
        const int h0 = t << 5;
        const float* apn = Ab + (size_t)(i0 + lr) * HH + h0 + lk;
        const float* cpn = Cb + (size_t)(j0 + lr) * HH + h0 + lk;
        av0 = *reinterpret_cast<const float4*>(apn);
        av1 = *reinterpret_cast<const float4*>(apn + 4);
        cv0 = *reinterpret_cast<const float4*>(cpn);
        cv1 = *reinterpret_cast<const float4*>(cpn + 4);

        const int hb = (t - 1) << 5;
        #pragma unroll
        for (int h = 0; h < 32; ++h) {
            float w = w2s[hb + h];
            float4 af = *reinterpret_cast<const float4*>(&aS[cur][h][ty << 2]);
            float4 cf = *reinterpret_cast<const float4*>(&cS[cur][h][tx << 2]);
            float ar[4] = {af.x, af.y, af.z, af.w};
            float cr[4] = {cf.x, cf.y, cf.z, cf.w};
            #pragma unroll
            for (int i = 0; i < 4; ++i)
                #pragma unroll
                for (int j = 0; j < 4; ++j)
                    acc[i][j] = fmaf(fmaxf(ar[i] + cr[j], 0.f), w, acc[i][j]);
        }
        const int nxt = cur ^ 1;
        aS[nxt][lk+0][lr]=av0.x; aS[nxt][lk+1][lr]=av0.y; aS[nxt][lk+2][lr]=av0.z; aS[nxt][lk+3][lr]=av0.w;
        aS[nxt][lk+4][lr]=av1.x; aS[nxt][lk+5][lr]=av1.y; aS[nxt][lk+6][lr]=av1.z; aS[nxt][lk+7][lr]=av1.w;
        cS[nxt][lk+0][lr]=cv0.x; cS[nxt][lk+1][lr]=cv0.y; cS[nxt][lk+2][lr]=cv0.z; cS[nxt][lk+3][lr]=cv0.w;
        cS[nxt][lk+4][lr]=cv1.x; cS[nxt][lk+5][lr]=cv1.y; cS[nxt][lk+6][lr]=cv1.z; cS[nxt][lk+7][lr]=cv1.w;
        __syncthreads();
        cur = nxt;
    }
    // last chunk (h base 224)
    #pragma unroll
    for (int h = 0; h < 32; ++h) {
        float w = w2s[224 + h];
        float4 af = *reinterpret_cast<const float4*>(&aS[cur][h][ty << 2]);
        float4 cf = *reinterpret_cast<const float4*>(&cS[cur][h][tx << 2]);
        float ar[4] = {af.x, af.y, af.z, af.w};
        float cr[4] = {cf.x, cf.y, cf.z, cf.w};
        #pragma unroll
        for (int i = 0; i < 4; ++i)
            #pragma unroll
            for (int j = 0; j < 4; ++j)
                acc[i][j] = fmaf(fmaxf(ar[i] + cr[j], 0.f), w, acc[i][j]);
    }

    const float b2 = b2p[0];
    #pragma unroll
    for (int i = 0; i < 4; ++i) {
        float s0 = acc[i][0] + b2, s1 = acc[i][1] + b2;
        float s2 = acc[i][2] + b2, s3 = acc[i][3] + b2;
        float4 o;
        o.x = 1.f / (1.f + __expf(-s0));
        o.y = 1.f / (1.f + __expf(-s1));
        o.z = 1.f / (1.f + __expf(-s2));
        o.w = 1.f / (1.f + __expf(-s3));
        *reinterpret_cast<float4*>(out + ((size_t)b * NNODE + i0 + (ty << 2) + i) * NNODE
                                       + j0 + (tx << 2)) = o;
    }
}

// ---------------- invariance reduction (deterministic two-stage tree) ----------------
__global__ __launch_bounds__(256) void reduce_stage1(const float* __restrict__ causal)
{
    const int p = blockIdx.x * 256 + threadIdx.x;   // (i,j) pair index
    float x[8];
    #pragma unroll
    for (int b = 0; b < 8; ++b) x[b] = causal[b * NMAT + p];
    float stab = 0.f, s = 0.f;
    #pragma unroll
    for (int b = 0; b < 8; ++b) { stab += fabsf(x[b] - x[(b + 7) & 7]); s += x[b]; }
    const float m = s * 0.125f;
    float var = 0.f;
    #pragma unroll
    for (int b = 0; b < 8; ++b) { float d = x[b] - m; var = fmaf(d, d, var); }
    float sd = sqrtf(var * (1.f / 7.f));   // ddof=1

    #pragma unroll
    for (int o = 16; o; o >>= 1) {
        stab += __shfl_down_sync(0xffffffffu, stab, o);
        sd   += __shfl_down_sync(0xffffffffu, sd, o);
    }
    __shared__ float sm[8][2];
    const int wid = threadIdx.x >> 5, lane = threadIdx.x & 31;
    if (lane == 0) { sm[wid][0] = stab; sm[wid][1] = sd; }
    __syncthreads();
    if (threadIdx.x == 0) {
        float a = 0.f, c = 0.f;
        #pragma unroll
        for (int w = 0; w < 8; ++w) { a += sm[w][0]; c += sm[w][1]; }
        g_partial[blockIdx.x * 2 + 0] = a;
        g_partial[blockIdx.x * 2 + 1] = c;
    }
}

__global__ __launch_bounds__(256) void reduce_stage2(float* __restrict__ inv)
{
    float a = g_partial[threadIdx.x * 2 + 0];
    float c = g_partial[threadIdx.x * 2 + 1];
    #pragma unroll
    for (int o = 16; o; o >>= 1) {
        a += __shfl_down_sync(0xffffffffu, a, o);
        c += __shfl_down_sync(0xffffffffu, c, o);
    }
    __shared__ float sm[8][2];
    const int wid = threadIdx.x >> 5, lane = threadIdx.x & 31;
    if (lane == 0) { sm[wid][0] = a; sm[wid][1] = c; }
    __syncthreads();
    if (threadIdx.x == 0) {
        float sa = 0.f, sc = 0.f;
        #pragma unroll
        for (int w = 0; w < 8; ++w) { sa += sm[w][0]; sc += sm[w][1]; }
        const float stability   = sa / (8.f * 65536.f);
        const float consistency = sc / 65536.f;
        inv[0] = 1.f - (stability + consistency) * 0.5f;
    }
}

// ---------------- launch ----------------
extern "C" void kernel_launch(void* const* d_in, const int* in_sizes, int n_in,
                              void* d_out, int out_size)
{
    const float* img    = (const float*)d_in[0];
    const float* txt    = (const float*)d_in[1];
    const float* ft_W1  = (const float*)d_in[2];
    const float* ft_b1  = (const float*)d_in[3];
    const float* ft_W2  = (const float*)d_in[4];
    const float* ft_b2  = (const float*)d_in[5];
    const float* sl_W1a = (const float*)d_in[6];
    const float* sl_W1b = (const float*)d_in[7];
    const float* sl_b1  = (const float*)d_in[8];
    const float* sl_W2  = (const float*)d_in[9];
    const float* sl_b2  = (const float*)d_in[10];
    const float* cn_W1a = (const float*)d_in[11];
    const float* cn_W1b = (const float*)d_in[12];
    const float* cn_b1  = (const float*)d_in[13];
    const float* cn_W2  = (const float*)d_in[14];
    const float* cn_b2  = (const float*)d_in[15];

    float* outp      = (float*)d_out;
    float* structure = outp;
    float* causal    = outp + OUT_MAT;
    float* inv       = outp + 2 * OUT_MAT;

    float *x1, *h, *ac;
    cudaGetSymbolAddress((void**)&x1, g_x1);
    cudaGetSymbolAddress((void**)&h,  g_h);
    cudaGetSymbolAddress((void**)&ac, g_ac);

    const dim3 gemm_grid(M2 / 64, HH / 64);            // 64 x 4 = 256 blocks
    const dim3 pair_grid(NNODE / 64, NNODE / 64, BB);  // 4 x 4 x 8 = 128 blocks

    // stage 1: hidden = relu([img;txt] @ ft_W1 + ft_b1)   [4096,256]
    gemm2<<<gemm_grid, 256>>>(img, txt, ft_W1, ft_W1, ft_b1, ft_b1, x1, FF, 1);
    // stage 2: feats = hidden @ ft_W2 + ft_b2             [4096,256] = imgh|txth
    gemm2<<<gemm_grid, 256>>>(x1, x1 + (size_t)MM * HH, ft_W2, ft_W2, ft_b2, ft_b2, h, HH, 0);
    // stage 3: a = imgh @ sl_W1a + sl_b1 ; c = txth @ sl_W1b
    gemm2<<<gemm_grid, 256>>>(h, h + (size_t)MM * HH, sl_W1a, sl_W1b, sl_b1, nullptr, ac, HH, 0);
    // stage 4: structure
    pair_scores_kernel<<<pair_grid, 256>>>(ac, ac + (size_t)MM * HH, sl_W2, sl_b2, structure);
    // stage 5: a = structure @ cn_W1a + cn_b1 ; c = structure @ cn_W1b
    gemm2<<<gemm_grid, 256>>>(structure, structure, cn_W1a, cn_W1b, cn_b1, nullptr, ac, HH, 0);
    // stage 6: causal
    pair_scores_kernel<<<pair_grid, 256>>>(ac, ac + (size_t)MM * HH, cn_W2, cn_b2, causal);
    // stage 7: invariance
    reduce_stage1<<<256, 256>>>(causal);
    reduce_stage2<<<1, 256>>>(inv);
}

// round 3
// speedup vs baseline: 1.7302x; 1.3027x over previous
#include <cuda_runtime.h>
#include <math.h>

#define BB 8
#define NNODE 256
#define FF 512
#define HH 256
#define MM (BB*NNODE)        // 2048 rows per logical matrix
#define M2 (2*MM)            // 4096 rows per batched GEMM launch
#define NMAT (NNODE*NNODE)   // 65536
#define OUT_MAT (BB*NMAT)    // 524288

// ---------------- scratch ----------------
__device__ float g_x1[M2*HH];
__device__ float g_h [M2*HH];
__device__ float g_ac[M2*HH];
__device__ float g_partial[2*256];

__device__ __forceinline__ unsigned f2tf32(float f) {
    unsigned u;
    asm("cvt.rna.tf32.f32 %0, %1;" : "=r"(u) : "f"(f));
    return u;
}

// ---------------- tensor-core batched GEMM ----------------
// rows [0,2048): C = act(A0 @ W0 + b0); rows [2048,4096): act(A1 @ W1 + b1)
// 64x64 block tile, 256 thr (8 warps, 4m x 2n, warp tile 16x32),
// K chunked by 32, double-buffered smem, mma.sync m16n8k8 tf32.
__global__ __launch_bounds__(256) void gemm2_tc(
    const float* __restrict__ A0, const float* __restrict__ A1,
    const float* __restrict__ W0, const float* __restrict__ W1,
    const float* __restrict__ b0, const float* __restrict__ b1,
    float* __restrict__ C, int K, int do_relu)
{
    __shared__ unsigned As[2][64][36];   // [row][k], padded
    __shared__ unsigned Ws[2][32][68];   // [k][n], padded

    const int tid  = threadIdx.x;
    const int warp = tid >> 5, lane = tid & 31;
    const int g    = lane >> 2;          // 0..7
    const int tig  = lane & 3;           // 0..3
    const int wm   = warp >> 1;          // 0..3 -> m offset
    const int wn   = warp & 1;           // 0..1 -> n offset
    const int rm   = wm << 4;            // warp m base (0..48)
    const int cn   = wn << 5;            // warp n base (0 or 32)

    const int half = gridDim.x >> 1;
    const float* A; const float* W; const float* bias;
    int row0;
    if (blockIdx.x < half) { A = A0; W = W0; bias = b0; row0 = blockIdx.x << 6; }
    else                   { A = A1; W = W1; bias = b1; row0 = (blockIdx.x - half) << 6; }
    const int bn = blockIdx.y << 6;
    const int crow0 = blockIdx.x << 6;

    // global-load mapping (per 64x32 A chunk / 32x64 W chunk)
    const int aRow = tid >> 2;            // 0..63
    const int aCol = (tid & 3) << 3;      // 0,8,16,24
    const int wRow = tid >> 3;            // 0..31
    const int wCol = (tid & 7) << 3;      // 0..56

    float acc[4][4] = {};                 // [n-frag][c0..c3]

    const int nk = K >> 5;                // chunks of 32

    // prologue: chunk 0
    {
        const float* ap = A + (size_t)(row0 + aRow) * K + aCol;
        const float* wp = W + (size_t)wRow * HH + bn + wCol;
        float4 a0 = *reinterpret_cast<const float4*>(ap);
        float4 a1 = *reinterpret_cast<const float4*>(ap + 4);
        float4 w0 = *reinterpret_cast<const float4*>(wp);
        float4 w1 = *reinterpret_cast<const float4*>(wp + 4);
        As[0][aRow][aCol+0]=f2tf32(a0.x); As[0][aRow][aCol+1]=f2tf32(a0.y);
        As[0][aRow][aCol+2]=f2tf32(a0.z); As[0][aRow][aCol+3]=f2tf32(a0.w);
        As[0][aRow][aCol+4]=f2tf32(a1.x); As[0][aRow][aCol+5]=f2tf32(a1.y);
        As[0][aRow][aCol+6]=f2tf32(a1.z); As[0][aRow][aCol+7]=f2tf32(a1.w);
        Ws[0][wRow][wCol+0]=f2tf32(w0.x); Ws[0][wRow][wCol+1]=f2tf32(w0.y);
        Ws[0][wRow][wCol+2]=f2tf32(w0.z); Ws[0][wRow][wCol+3]=f2tf32(w0.w);
        Ws[0][wRow][wCol+4]=f2tf32(w1.x); Ws[0][wRow][wCol+5]=f2tf32(w1.y);
        Ws[0][wRow][wCol+6]=f2tf32(w1.z); Ws[0][wRow][wCol+7]=f2tf32(w1.w);
    }
    __syncthreads();

    int cur = 0;
    for (int t = 1; t <= nk; ++t) {
        float4 a0, a1, w0, w1;
        const bool has_next = (t < nk);
        if (has_next) {
            const int k0 = t << 5;
            const float* ap = A + (size_t)(row0 + aRow) * K + k0 + aCol;
            const float* wp = W + (size_t)(k0 + wRow) * HH + bn + wCol;
            a0 = *reinterpret_cast<const float4*>(ap);
            a1 = *reinterpret_cast<const float4*>(ap + 4);
            w0 = *reinterpret_cast<const float4*>(wp);
            w1 = *reinterpret_cast<const float4*>(wp + 4);
        }
        // compute on current buffer: 4 k8-steps
        #pragma unroll
        for (int k8 = 0; k8 < 4; ++k8) {
            const int k0 = k8 << 3;
            unsigned fa0 = As[cur][rm + g    ][k0 + tig];
            unsigned fa1 = As[cur][rm + 8 + g][k0 + tig];
            unsigned fa2 = As[cur][rm + g    ][k0 + 4 + tig];
            unsigned fa3 = As[cur][rm + 8 + g][k0 + 4 + tig];
            #pragma unroll
            for (int nf = 0; nf < 4; ++nf) {
                const int n0 = cn + (nf << 3);
                unsigned fb0 = Ws[cur][k0 + tig    ][n0 + g];
                unsigned fb1 = Ws[cur][k0 + 4 + tig][n0 + g];
                asm volatile(
                    "mma.sync.aligned.m16n8k8.row.col.f32.tf32.tf32.f32 "
                    "{%0,%1,%2,%3}, {%4,%5,%6,%7}, {%8,%9}, {%0,%1,%2,%3};"
                    : "+f"(acc[nf][0]), "+f"(acc[nf][1]),
                      "+f"(acc[nf][2]), "+f"(acc[nf][3])
                    : "r"(fa0), "r"(fa1), "r"(fa2), "r"(fa3),
                      "r"(fb0), "r"(fb1));
            }
        }
        if (has_next) {
            const int nxt = cur ^ 1;
            As[nxt][aRow][aCol+0]=f2tf32(a0.x); As[nxt][aRow][aCol+1]=f2tf32(a0.y);
            As[nxt][aRow][aCol+2]=f2tf32(a0.z); As[nxt][aRow][aCol+3]=f2tf32(a0.w);
            As[nxt][aRow][aCol+4]=f2tf32(a1.x); As[nxt][aRow][aCol+5]=f2tf32(a1.y);
            As[nxt][aRow][aCol+6]=f2tf32(a1.z); As[nxt][aRow][aCol+7]=f2tf32(a1.w);
            Ws[nxt][wRow][wCol+0]=f2tf32(w0.x); Ws[nxt][wRow][wCol+1]=f2tf32(w0.y);
            Ws[nxt][wRow][wCol+2]=f2tf32(w0.z); Ws[nxt][wRow][wCol+3]=f2tf32(w0.w);
            Ws[nxt][wRow][wCol+4]=f2tf32(w1.x); Ws[nxt][wRow][wCol+5]=f2tf32(w1.y);
            Ws[nxt][wRow][wCol+6]=f2tf32(w1.z); Ws[nxt][wRow][wCol+7]=f2tf32(w1.w);
            __syncthreads();
            cur = nxt;
        }
    }

    // epilogue
    #pragma unroll
    for (int nf = 0; nf < 4; ++nf) {
        const int col = bn + cn + (nf << 3) + (tig << 1);
        float bx = 0.f, by = 0.f;
        if (bias) { bx = bias[col]; by = bias[col + 1]; }
        const int r0 = crow0 + rm + g;
        const int r1 = r0 + 8;
        float v0 = acc[nf][0] + bx, v1 = acc[nf][1] + by;
        float v2 = acc[nf][2] + bx, v3 = acc[nf][3] + by;
        if (do_relu) {
            v0 = fmaxf(v0, 0.f); v1 = fmaxf(v1, 0.f);
            v2 = fmaxf(v2, 0.f); v3 = fmaxf(v3, 0.f);
        }
        float2 o01; o01.x = v0; o01.y = v1;
        float2 o23; o23.x = v2; o23.y = v3;
        *reinterpret_cast<float2*>(C + (size_t)r0 * HH + col) = o01;
        *reinterpret_cast<float2*>(C + (size_t)r1 * HH + col) = o23;
    }
}

// ---------------- pairwise: out[b,i,j] = sigmoid( sum_h relu(a[i,h]+c[j,h]) * w2[h] + b2 )
// 64i x 32j tile (256 blocks -> 2 CTA/SM), h chunks of 32, double-buffered.
__global__ __launch_bounds__(256) void pair_scores_kernel(
    const float* __restrict__ Aa, const float* __restrict__ Cc,
    const float* __restrict__ w2, const float* __restrict__ b2p,
    float* __restrict__ out)
{
    __shared__ float aS[2][32][64];   // [h][i]
    __shared__ float cS[2][32][32];   // [h][j]
    __shared__ float w2s[HH];

    const int tid = threadIdx.x;
    const int tx = tid & 15, ty = tid >> 4;
    const int i0 = blockIdx.x << 6, j0 = blockIdx.y << 5;
    const int b  = blockIdx.z;
    w2s[tid] = w2[tid];

    const int aRow = tid >> 2;            // 0..63
    const int ah   = (tid & 3) << 3;      // 0,8,16,24
    const int cRow = tid >> 3;            // 0..31
    const int ch   = (tid & 7) << 2;      // 0..28

    const float* Ab = Aa + (size_t)b * NNODE * HH;
    const float* Cb = Cc + (size_t)b * NNODE * HH;
    float acc[4][2] = {};

    // prologue chunk 0
    {
        const float* ap = Ab + (size_t)(i0 + aRow) * HH + ah;
        const float* cp = Cb + (size_t)(j0 + cRow) * HH + ch;
        float4 av0 = *reinterpret_cast<const float4*>(ap);
        float4 av1 = *reinterpret_cast<const float4*>(ap + 4);
        float4 cv  = *reinterpret_cast<const float4*>(cp);
        aS[0][ah+0][aRow]=av0.x; aS[0][ah+1][aRow]=av0.y; aS[0][ah+2][aRow]=av0.z; aS[0][ah+3][aRow]=av0.w;
        aS[0][ah+4][aRow]=av1.x; aS[0][ah+5][aRow]=av1.y; aS[0][ah+6][aRow]=av1.z; aS[0][ah+7][aRow]=av1.w;
        cS[0][ch+0][cRow]=cv.x;  cS[0][ch+1][cRow]=cv.y;  cS[0][ch+2][cRow]=cv.z;  cS[0][ch+3][cRow]=cv.w;
    }
    __syncthreads();

    int cur = 0;
    for (int t = 1; t <= 8; ++t) {
        float4 av0, av1, cv;
        const bool has_next = (t < 8);
        if (has_next) {
            const int h0 = t << 5;
            const float* ap = Ab + (size_t)(i0 + aRow) * HH + h0 + ah;
            const float* cp = Cb + (size_t)(j0 + cRow) * HH + h0 + ch;
            av0 = *reinterpret_cast<const float4*>(ap);
            av1 = *reinterpret_cast<const float4*>(ap + 4);
            cv  = *reinterpret_cast<const float4*>(cp);
        }
        const int hb = (t - 1) << 5;
        #pragma unroll
        for (int h = 0; h < 32; ++h) {
            float w = w2s[hb + h];
            float4 af = *reinterpret_cast<const float4*>(&aS[cur][h][ty << 2]);
            float2 cf = *reinterpret_cast<const float2*>(&cS[cur][h][tx << 1]);
            float ar[4] = {af.x, af.y, af.z, af.w};
            float cr[2] = {cf.x, cf.y};
            #pragma unroll
            for (int i = 0; i < 4; ++i)
                #pragma unroll
                for (int j = 0; j < 2; ++j)
                    acc[i][j] = fmaf(fmaxf(ar[i] + cr[j], 0.f), w, acc[i][j]);
        }
        if (has_next) {
            const int nxt = cur ^ 1;
            aS[nxt][ah+0][aRow]=av0.x; aS[nxt][ah+1][aRow]=av0.y; aS[nxt][ah+2][aRow]=av0.z; aS[nxt][ah+3][aRow]=av0.w;
            aS[nxt][ah+4][aRow]=av1.x; aS[nxt][ah+5][aRow]=av1.y; aS[nxt][ah+6][aRow]=av1.z; aS[nxt][ah+7][aRow]=av1.w;
            cS[nxt][ch+0][cRow]=cv.x;  cS[nxt][ch+1][cRow]=cv.y;  cS[nxt][ch+2][cRow]=cv.z;  cS[nxt][ch+3][cRow]=cv.w;
            __syncthreads();
            cur = nxt;
        }
    }

    const float b2 = b2p[0];
    #pragma unroll
    for (int i = 0; i < 4; ++i) {
        float s0 = acc[i][0] + b2, s1 = acc[i][1] + b2;
        float2 o;
        o.x = 1.f / (1.f + __expf(-s0));
        o.y = 1.f / (1.f + __expf(-s1));
        *reinterpret_cast<float2*>(out + ((size_t)b * NNODE + i0 + (ty << 2) + i) * NNODE
                                       + j0 + (tx << 1)) = o;
    }
}

// ---------------- invariance reduction ----------------
__global__ __launch_bounds__(256) void reduce_stage1(const float* __restrict__ causal)
{
    const int p = blockIdx.x * 256 + threadIdx.x;
    float x[8];
    #pragma unroll
    for (int b = 0; b < 8; ++b) x[b] = causal[b * NMAT + p];
    float stab = 0.f, s = 0.f;
    #pragma unroll
    for (int b = 0; b < 8; ++b) { stab += fabsf(x[b] - x[(b + 7) & 7]); s += x[b]; }
    const float m = s * 0.125f;
    float var = 0.f;
    #pragma unroll
    for (int b = 0; b < 8; ++b) { float d = x[b] - m; var = fmaf(d, d, var); }
    float sd = sqrtf(var * (1.f / 7.f));

    #pragma unroll
    for (int o = 16; o; o >>= 1) {
        stab += __shfl_down_sync(0xffffffffu, stab, o);
        sd   += __shfl_down_sync(0xffffffffu, sd, o);
    }
    __shared__ float sm[8][2];
    const int wid = threadIdx.x >> 5, lane = threadIdx.x & 31;
    if (lane == 0) { sm[wid][0] = stab; sm[wid][1] = sd; }
    __syncthreads();
    if (threadIdx.x == 0) {
        float a = 0.f, c = 0.f;
        #pragma unroll
        for (int w = 0; w < 8; ++w) { a += sm[w][0]; c += sm[w][1]; }
        g_partial[blockIdx.x * 2 + 0] = a;
        g_partial[blockIdx.x * 2 + 1] = c;
    }
}

__global__ __launch_bounds__(256) void reduce_stage2(float* __restrict__ inv)
{
    float a = g_partial[threadIdx.x * 2 + 0];
    float c = g_partial[threadIdx.x * 2 + 1];
    #pragma unroll
    for (int o = 16; o; o >>= 1) {
        a += __shfl_down_sync(0xffffffffu, a, o);
        c += __shfl_down_sync(0xffffffffu, c, o);
    }
    __shared__ float sm[8][2];
    const int wid = threadIdx.x >> 5, lane = threadIdx.x & 31;
    if (lane == 0) { sm[wid][0] = a; sm[wid][1] = c; }
    __syncthreads();
    if (threadIdx.x == 0) {
        float sa = 0.f, sc = 0.f;
        #pragma unroll
        for (int w = 0; w < 8; ++w) { sa += sm[w][0]; sc += sm[w][1]; }
        const float stability   = sa / (8.f * 65536.f);
        const float consistency = sc / 65536.f;
        inv[0] = 1.f - (stability + consistency) * 0.5f;
    }
}

// ---------------- launch ----------------
extern "C" void kernel_launch(void* const* d_in, const int* in_sizes, int n_in,
                              void* d_out, int out_size)
{
    const float* img    = (const float*)d_in[0];
    const float* txt    = (const float*)d_in[1];
    const float* ft_W1  = (const float*)d_in[2];
    const float* ft_b1  = (const float*)d_in[3];
    const float* ft_W2  = (const float*)d_in[4];
    const float* ft_b2  = (const float*)d_in[5];
    const float* sl_W1a = (const float*)d_in[6];
    const float* sl_W1b = (const float*)d_in[7];
    const float* sl_b1  = (const float*)d_in[8];
    const float* sl_W2  = (const float*)d_in[9];
    const float* sl_b2  = (const float*)d_in[10];
    const float* cn_W1a = (const float*)d_in[11];
    const float* cn_W1b = (const float*)d_in[12];
    const float* cn_b1  = (const float*)d_in[13];
    const float* cn_W2  = (const float*)d_in[14];
    const float* cn_b2  = (const float*)d_in[15];

    float* outp      = (float*)d_out;
    float* structure = outp;
    float* causal    = outp + OUT_MAT;
    float* inv       = outp + 2 * OUT_MAT;

    float *x1, *h, *ac;
    cudaGetSymbolAddress((void**)&x1, g_x1);
    cudaGetSymbolAddress((void**)&h,  g_h);
    cudaGetSymbolAddress((void**)&ac, g_ac);

    const dim3 gemm_grid(M2 / 64, HH / 64);            // 64 x 4 = 256 blocks
    const dim3 pair_grid(NNODE / 64, NNODE / 32, BB);  // 4 x 8 x 8 = 256 blocks

    gemm2_tc<<<gemm_grid, 256>>>(img, txt, ft_W1, ft_W1, ft_b1, ft_b1, x1, FF, 1);
    gemm2_tc<<<gemm_grid, 256>>>(x1, x1 + (size_t)MM * HH, ft_W2, ft_W2, ft_b2, ft_b2, h, HH, 0);
    gemm2_tc<<<gemm_grid, 256>>>(h, h + (size_t)MM * HH, sl_W1a, sl_W1b, sl_b1, nullptr, ac, HH, 0);
    pair_scores_kernel<<<pair_grid, 256>>>(ac, ac + (size_t)MM * HH, sl_W2, sl_b2, structure);
    gemm2_tc<<<gemm_grid, 256>>>(structure, structure, cn_W1a, cn_W1b, cn_b1, nullptr, ac, HH, 0);
    pair_scores_kernel<<<pair_grid, 256>>>(ac, ac + (size_t)MM * HH, cn_W2, cn_b2, causal);
    reduce_stage1<<<256, 256>>>(causal);
    reduce_stage2<<<1, 256>>>(inv);
}

// round 4
// speedup vs baseline: 1.7332x; 1.0018x over previous
#include <cuda_runtime.h>
#include <math.h>

#define BB 8
#define NNODE 256
#define FF 512
#define HH 256
#define MM (BB*NNODE)        // 2048 rows per logical matrix
#define M2 (2*MM)            // 4096 rows per batched GEMM launch
#define NMAT (NNODE*NNODE)   // 65536
#define OUT_MAT (BB*NMAT)    // 524288

// ---------------- scratch ----------------
__device__ float g_x1[M2*HH];
__device__ float g_h [M2*HH];
__device__ float g_ac[M2*HH];
__device__ float g_partial[2*256];

__device__ __forceinline__ unsigned f2tf32(float f) {
    unsigned u;
    asm("cvt.rna.tf32.f32 %0, %1;" : "=r"(u) : "f"(f));
    return u;
}

// ---------------- tensor-core batched GEMM ----------------
// rows [0,2048): C = act(A0 @ W0 + b0); rows [2048,4096): act(A1 @ W1 + b1)
// 64x64 block tile, 256 thr (8 warps, 4m x 2n, warp tile 16x32),
// K chunked by 32, double-buffered smem, mma.sync m16n8k8 tf32.
__global__ __launch_bounds__(256) void gemm2_tc(
    const float* __restrict__ A0, const float* __restrict__ A1,
    const float* __restrict__ W0, const float* __restrict__ W1,
    const float* __restrict__ b0, const float* __restrict__ b1,
    float* __restrict__ C, int K, int do_relu)
{
    __shared__ unsigned As[2][64][36];   // [row][k], padded
    __shared__ unsigned Ws[2][32][68];   // [k][n], padded

    const int tid  = threadIdx.x;
    const int warp = tid >> 5, lane = tid & 31;
    const int g    = lane >> 2;          // 0..7
    const int tig  = lane & 3;           // 0..3
    const int wm   = warp >> 1;          // 0..3 -> m offset
    const int wn   = warp & 1;           // 0..1 -> n offset
    const int rm   = wm << 4;            // warp m base (0..48)
    const int cn   = wn << 5;            // warp n base (0 or 32)

    const int half = gridDim.x >> 1;
    const float* A; const float* W; const float* bias;
    int row0;
    if (blockIdx.x < half) { A = A0; W = W0; bias = b0; row0 = blockIdx.x << 6; }
    else                   { A = A1; W = W1; bias = b1; row0 = (blockIdx.x - half) << 6; }
    const int bn = blockIdx.y << 6;
    const int crow0 = blockIdx.x << 6;

    // global-load mapping (per 64x32 A chunk / 32x64 W chunk)
    const int aRow = tid >> 2;            // 0..63
    const int aCol = (tid & 3) << 3;      // 0,8,16,24
    const int wRow = tid >> 3;            // 0..31
    const int wCol = (tid & 7) << 3;      // 0..56

    float acc[4][4] = {};                 // [n-frag][c0..c3]

    const int nk = K >> 5;                // chunks of 32

    // prologue: chunk 0
    {
        const float* ap = A + (size_t)(row0 + aRow) * K + aCol;
        const float* wp = W + (size_t)wRow * HH + bn + wCol;
        float4 a0 = *reinterpret_cast<const float4*>(ap);
        float4 a1 = *reinterpret_cast<const float4*>(ap + 4);
        float4 w0 = *reinterpret_cast<const float4*>(wp);
        float4 w1 = *reinterpret_cast<const float4*>(wp + 4);
        As[0][aRow][aCol+0]=f2tf32(a0.x); As[0][aRow][aCol+1]=f2tf32(a0.y);
        As[0][aRow][aCol+2]=f2tf32(a0.z); As[0][aRow][aCol+3]=f2tf32(a0.w);
        As[0][aRow][aCol+4]=f2tf32(a1.x); As[0][aRow][aCol+5]=f2tf32(a1.y);
        As[0][aRow][aCol+6]=f2tf32(a1.z); As[0][aRow][aCol+7]=f2tf32(a1.w);
        Ws[0][wRow][wCol+0]=f2tf32(w0.x); Ws[0][wRow][wCol+1]=f2tf32(w0.y);
        Ws[0][wRow][wCol+2]=f2tf32(w0.z); Ws[0][wRow][wCol+3]=f2tf32(w0.w);
        Ws[0][wRow][wCol+4]=f2tf32(w1.x); Ws[0][wRow][wCol+5]=f2tf32(w1.y);
        Ws[0][wRow][wCol+6]=f2tf32(w1.z); Ws[0][wRow][wCol+7]=f2tf32(w1.w);
    }
    __syncthreads();

    int cur = 0;
    for (int t = 1; t <= nk; ++t) {
        float4 a0, a1, w0, w1;
        const bool has_next = (t < nk);
        if (has_next) {
            const int k0 = t << 5;
            const float* ap = A + (size_t)(row0 + aRow) * K + k0 + aCol;
            const float* wp = W + (size_t)(k0 + wRow) * HH + bn + wCol;
            a0 = *reinterpret_cast<const float4*>(ap);
            a1 = *reinterpret_cast<const float4*>(ap + 4);
            w0 = *reinterpret_cast<const float4*>(wp);
            w1 = *reinterpret_cast<const float4*>(wp + 4);
        }
        // compute on current buffer: 4 k8-steps
        #pragma unroll
        for (int k8 = 0; k8 < 4; ++k8) {
            const int k0 = k8 << 3;
            unsigned fa0 = As[cur][rm + g    ][k0 + tig];
            unsigned fa1 = As[cur][rm + 8 + g][k0 + tig];
            unsigned fa2 = As[cur][rm + g    ][k0 + 4 + tig];
            unsigned fa3 = As[cur][rm + 8 + g][k0 + 4 + tig];
            #pragma unroll
            for (int nf = 0; nf < 4; ++nf) {
                const int n0 = cn + (nf << 3);
                unsigned fb0 = Ws[cur][k0 + tig    ][n0 + g];
                unsigned fb1 = Ws[cur][k0 + 4 + tig][n0 + g];
                asm volatile(
                    "mma.sync.aligned.m16n8k8.row.col.f32.tf32.tf32.f32 "
                    "{%0,%1,%2,%3}, {%4,%5,%6,%7}, {%8,%9}, {%0,%1,%2,%3};"
                    : "+f"(acc[nf][0]), "+f"(acc[nf][1]),
                      "+f"(acc[nf][2]), "+f"(acc[nf][3])
                    : "r"(fa0), "r"(fa1), "r"(fa2), "r"(fa3),
                      "r"(fb0), "r"(fb1));
            }
        }
        if (has_next) {
            const int nxt = cur ^ 1;
            As[nxt][aRow][aCol+0]=f2tf32(a0.x); As[nxt][aRow][aCol+1]=f2tf32(a0.y);
            As[nxt][aRow][aCol+2]=f2tf32(a0.z); As[nxt][aRow][aCol+3]=f2tf32(a0.w);
            As[nxt][aRow][aCol+4]=f2tf32(a1.x); As[nxt][aRow][aCol+5]=f2tf32(a1.y);
            As[nxt][aRow][aCol+6]=f2tf32(a1.z); As[nxt][aRow][aCol+7]=f2tf32(a1.w);
            Ws[nxt][wRow][wCol+0]=f2tf32(w0.x); Ws[nxt][wRow][wCol+1]=f2tf32(w0.y);
            Ws[nxt][wRow][wCol+2]=f2tf32(w0.z); Ws[nxt][wRow][wCol+3]=f2tf32(w0.w);
            Ws[nxt][wRow][wCol+4]=f2tf32(w1.x); Ws[nxt][wRow][wCol+5]=f2tf32(w1.y);
            Ws[nxt][wRow][wCol+6]=f2tf32(w1.z); Ws[nxt][wRow][wCol+7]=f2tf32(w1.w);
            __syncthreads();
            cur = nxt;
        }
    }

    // epilogue
    #pragma unroll
    for (int nf = 0; nf < 4; ++nf) {
        const int col = bn + cn + (nf << 3) + (tig << 1);
        float bx = 0.f, by = 0.f;
        if (bias) { bx = bias[col]; by = bias[col + 1]; }
        const int r0 = crow0 + rm + g;
        const int r1 = r0 + 8;
        float v0 = acc[nf][0] + bx, v1 = acc[nf][1] + by;
        float v2 = acc[nf][2] + bx, v3 = acc[nf][3] + by;
        if (do_relu) {
            v0 = fmaxf(v0, 0.f); v1 = fmaxf(v1, 0.f);
            v2 = fmaxf(v2, 0.f); v3 = fmaxf(v3, 0.f);
        }
        float2 o01; o01.x = v0; o01.y = v1;
        float2 o23; o23.x = v2; o23.y = v3;
        *reinterpret_cast<float2*>(C + (size_t)r0 * HH + col) = o01;
        *reinterpret_cast<float2*>(C + (size_t)r1 * HH + col) = o23;
    }
}

// ---------------- pairwise: out[b,i,j] = sigmoid( sum_h relu(a[i,h]+c[j,h]) * w2[h] + b2 )
// 64i x 32j tile (256 blocks -> 2 CTA/SM), h chunks of 32, double-buffered.
__global__ __launch_bounds__(256) void pair_scores_kernel(
    const float* __restrict__ Aa, const float* __restrict__ Cc,
    const float* __restrict__ w2, const float* __restrict__ b2p,
    float* __restrict__ out)
{
    __shared__ float aS[2][32][64];   // [h][i]
    __shared__ float cS[2][32][32];   // [h][j]
    __shared__ float w2s[HH];

    const int tid = threadIdx.x;
    const int tx = tid & 15, ty = tid >> 4;
    const int i0 = blockIdx.x << 6, j0 = blockIdx.y << 5;
    const int b  = blockIdx.z;
    w2s[tid] = w2[tid];

    const int aRow = tid >> 2;            // 0..63
    const int ah   = (tid & 3) << 3;      // 0,8,16,24
    const int cRow = tid >> 3;            // 0..31
    const int ch   = (tid & 7) << 2;      // 0..28

    const float* Ab = Aa + (size_t)b * NNODE * HH;
    const float* Cb = Cc + (size_t)b * NNODE * HH;
    float acc[4][2] = {};

    // prologue chunk 0
    {
        const float* ap = Ab + (size_t)(i0 + aRow) * HH + ah;
        const float* cp = Cb + (size_t)(j0 + cRow) * HH + ch;
        float4 av0 = *reinterpret_cast<const float4*>(ap);
        float4 av1 = *reinterpret_cast<const float4*>(ap + 4);
        float4 cv  = *reinterpret_cast<const float4*>(cp);
        aS[0][ah+0][aRow]=av0.x; aS[0][ah+1][aRow]=av0.y; aS[0][ah+2][aRow]=av0.z; aS[0][ah+3][aRow]=av0.w;
        aS[0][ah+4][aRow]=av1.x; aS[0][ah+5][aRow]=av1.y; aS[0][ah+6][aRow]=av1.z; aS[0][ah+7][aRow]=av1.w;
        cS[0][ch+0][cRow]=cv.x;  cS[0][ch+1][cRow]=cv.y;  cS[0][ch+2][cRow]=cv.z;  cS[0][ch+3][cRow]=cv.w;
    }
    __syncthreads();

    int cur = 0;
    for (int t = 1; t <= 8; ++t) {
        float4 av0, av1, cv;
        const bool has_next = (t < 8);
        if (has_next) {
            const int h0 = t << 5;
            const float* ap = Ab + (size_t)(i0 + aRow) * HH + h0 + ah;
            const float* cp = Cb + (size_t)(j0 + cRow) * HH + h0 + ch;
            av0 = *reinterpret_cast<const float4*>(ap);
            av1 = *reinterpret_cast<const float4*>(ap + 4);
            cv  = *reinterpret_cast<const float4*>(cp);
        }
        const int hb = (t - 1) << 5;
        #pragma unroll
        for (int h = 0; h < 32; ++h) {
            float w = w2s[hb + h];
            float4 af = *reinterpret_cast<const float4*>(&aS[cur][h][ty << 2]);
            float2 cf = *reinterpret_cast<const float2*>(&cS[cur][h][tx << 1]);
            float ar[4] = {af.x, af.y, af.z, af.w};
            float cr[2] = {cf.x, cf.y};
            #pragma unroll
            for (int i = 0; i < 4; ++i)
                #pragma unroll
                for (int j = 0; j < 2; ++j)
                    acc[i][j] = fmaf(fmaxf(ar[i] + cr[j], 0.f), w, acc[i][j]);
        }
        if (has_next) {
            const int nxt = cur ^ 1;
            aS[nxt][ah+0][aRow]=av0.x; aS[nxt][ah+1][aRow]=av0.y; aS[nxt][ah+2][aRow]=av0.z; aS[nxt][ah+3][aRow]=av0.w;
            aS[nxt][ah+4][aRow]=av1.x; aS[nxt][ah+5][aRow]=av1.y; aS[nxt][ah+6][aRow]=av1.z; aS[nxt][ah+7][aRow]=av1.w;
            cS[nxt][ch+0][cRow]=cv.x;  cS[nxt][ch+1][cRow]=cv.y;  cS[nxt][ch+2][cRow]=cv.z;  cS[nxt][ch+3][cRow]=cv.w;
            __syncthreads();
            cur = nxt;
        }
    }

    const float b2 = b2p[0];
    #pragma unroll
    for (int i = 0; i < 4; ++i) {
        float s0 = acc[i][0] + b2, s1 = acc[i][1] + b2;
        float2 o;
        o.x = 1.f / (1.f + __expf(-s0));
        o.y = 1.f / (1.f + __expf(-s1));
        *reinterpret_cast<float2*>(out + ((size_t)b * NNODE + i0 + (ty << 2) + i) * NNODE
                                       + j0 + (tx << 1)) = o;
    }
}

// ---------------- invariance reduction ----------------
__global__ __launch_bounds__(256) void reduce_stage1(const float* __restrict__ causal)
{
    const int p = blockIdx.x * 256 + threadIdx.x;
    float x[8];
    #pragma unroll
    for (int b = 0; b < 8; ++b) x[b] = causal[b * NMAT + p];
    float stab = 0.f, s = 0.f;
    #pragma unroll
    for (int b = 0; b < 8; ++b) { stab += fabsf(x[b] - x[(b + 7) & 7]); s += x[b]; }
    const float m = s * 0.125f;
    float var = 0.f;
    #pragma unroll
    for (int b = 0; b < 8; ++b) { float d = x[b] - m; var = fmaf(d, d, var); }
    float sd = sqrtf(var * (1.f / 7.f));

    #pragma unroll
    for (int o = 16; o; o >>= 1) {
        stab += __shfl_down_sync(0xffffffffu, stab, o);
        sd   += __shfl_down_sync(0xffffffffu, sd, o);
    }
    __shared__ float sm[8][2];
    const int wid = threadIdx.x >> 5, lane = threadIdx.x & 31;
    if (lane == 0) { sm[wid][0] = stab; sm[wid][1] = sd; }
    __syncthreads();
    if (threadIdx.x == 0) {
        float a = 0.f, c = 0.f;
        #pragma unroll
        for (int w = 0; w < 8; ++w) { a += sm[w][0]; c += sm[w][1]; }
        g_partial[blockIdx.x * 2 + 0] = a;
        g_partial[blockIdx.x * 2 + 1] = c;
    }
}

__global__ __launch_bounds__(256) void reduce_stage2(float* __restrict__ inv)
{
    float a = g_partial[threadIdx.x * 2 + 0];
    float c = g_partial[threadIdx.x * 2 + 1];
    #pragma unroll
    for (int o = 16; o; o >>= 1) {
        a += __shfl_down_sync(0xffffffffu, a, o);
        c += __shfl_down_sync(0xffffffffu, c, o);
    }
    __shared__ float sm[8][2];
    const int wid = threadIdx.x >> 5, lane = threadIdx.x & 31;
    if (lane == 0) { sm[wid][0] = a; sm[wid][1] = c; }
    __syncthreads();
    if (threadIdx.x == 0) {
        float sa = 0.f, sc = 0.f;
        #pragma unroll
        for (int w = 0; w < 8; ++w) { sa += sm[w][0]; sc += sm[w][1]; }
        const float stability   = sa / (8.f * 65536.f);
        const float consistency = sc / 65536.f;
        inv[0] = 1.f - (stability + consistency) * 0.5f;
    }
}

// ---------------- launch ----------------
extern "C" void kernel_launch(void* const* d_in, const int* in_sizes, int n_in,
                              void* d_out, int out_size)
{
    const float* img    = (const float*)d_in[0];
    const float* txt    = (const float*)d_in[1];
    const float* ft_W1  = (const float*)d_in[2];
    const float* ft_b1  = (const float*)d_in[3];
    const float* ft_W2  = (const float*)d_in[4];
    const float* ft_b2  = (const float*)d_in[5];
    const float* sl_W1a = (const float*)d_in[6];
    const float* sl_W1b = (const float*)d_in[7];
    const float* sl_b1  = (const float*)d_in[8];
    const float* sl_W2  = (const float*)d_in[9];
    const float* sl_b2  = (const float*)d_in[10];
    const float* cn_W1a = (const float*)d_in[11];
    const float* cn_W1b = (const float*)d_in[12];
    const float* cn_b1  = (const float*)d_in[13];
    const float* cn_W2  = (const float*)d_in[14];
    const float* cn_b2  = (const float*)d_in[15];

    float* outp      = (float*)d_out;
    float* structure = outp;
    float* causal    = outp + OUT_MAT;
    float* inv       = outp + 2 * OUT_MAT;

    float *x1, *h, *ac;
    cudaGetSymbolAddress((void**)&x1, g_x1);
    cudaGetSymbolAddress((void**)&h,  g_h);
    cudaGetSymbolAddress((void**)&ac, g_ac);

    const dim3 gemm_grid(M2 / 64, HH / 64);            // 64 x 4 = 256 blocks
    const dim3 pair_grid(NNODE / 64, NNODE / 32, BB);  // 4 x 8 x 8 = 256 blocks

    gemm2_tc<<<gemm_grid, 256>>>(img, txt, ft_W1, ft_W1, ft_b1, ft_b1, x1, FF, 1);
    gemm2_tc<<<gemm_grid, 256>>>(x1, x1 + (size_t)MM * HH, ft_W2, ft_W2, ft_b2, ft_b2, h, HH, 0);
    gemm2_tc<<<gemm_grid, 256>>>(h, h + (size_t)MM * HH, sl_W1a, sl_W1b, sl_b1, nullptr, ac, HH, 0);
    pair_scores_kernel<<<pair_grid, 256>>>(ac, ac + (size_t)MM * HH, sl_W2, sl_b2, structure);
    gemm2_tc<<<gemm_grid, 256>>>(structure, structure, cn_W1a, cn_W1b, cn_b1, nullptr, ac, HH, 0);
    pair_scores_kernel<<<pair_grid, 256>>>(ac, ac + (size_t)MM * HH, cn_W2, cn_b2, causal);
    reduce_stage1<<<256, 256>>>(causal);
    reduce_stage2<<<1, 256>>>(inv);
}

// round 5
// speedup vs baseline: 1.7586x; 1.0146x over previous
#include <cuda_runtime.h>
#include <math.h>

#define BB 8
#define NNODE 256
#define FF 512
#define HH 256
#define MM 2048
#define M2 4096
#define NMAT 65536
#define OUT_MAT 524288

typedef unsigned long long ull;

// ---------------- scratch ----------------
__device__ float g_x1[M2*HH];
__device__ float g_h [M2*HH];
__device__ float g_ac[M2*HH];
__device__ float g_dots[M2];
__device__ float g_partial[2*256];

__device__ __forceinline__ unsigned f2tf32(float f) {
    unsigned u;
    asm("cvt.rna.tf32.f32 %0, %1;" : "=r"(u) : "f"(f));
    return u;
}

#define MMA_TF32(acc, fa0, fa1, fa2, fa3, fb0, fb1)                          \
    asm volatile(                                                            \
        "mma.sync.aligned.m16n8k8.row.col.f32.tf32.tf32.f32 "                \
        "{%0,%1,%2,%3}, {%4,%5,%6,%7}, {%8,%9}, {%0,%1,%2,%3};"              \
        : "+f"((acc)[0]), "+f"((acc)[1]), "+f"((acc)[2]), "+f"((acc)[3])     \
        : "r"(fa0), "r"(fa1), "r"(fa2), "r"(fa3), "r"(fb0), "r"(fb1))

// ---------------- tensor-core batched GEMM ----------------
// rows [0,2048): C = act(A0 @ W0 + b0); rows [2048,4096): act(A1 @ W1 + b1)
// 128x64 block tile, 256 thr = 8 warps (4m x 2n), warp tile 32x32.
// K chunked by 32, double-buffered XOR-swizzled smem, mma m16n8k8 tf32 (rna cvt).
__global__ __launch_bounds__(256) void gemm2_tc(
    const float* __restrict__ A0, const float* __restrict__ A1,
    const float* __restrict__ W0, const float* __restrict__ W1,
    const float* __restrict__ b0, const float* __restrict__ b1,
    float* __restrict__ C, int K, int do_relu)
{
    __shared__ unsigned As[2][128*32];   // [row][k], 4-elem groups XOR-swizzled by row&7
    __shared__ unsigned Ws[2][32*64];    // [k][n],  4-elem groups XOR-swizzled by (k&3)<<1

    const int tid  = threadIdx.x;
    const int warp = tid >> 5, lane = tid & 31;
    const int g    = lane >> 2;          // 0..7
    const int tig  = lane & 3;           // 0..3
    const int wm   = warp >> 1;          // 0..3
    const int wn   = warp & 1;           // 0..1

    const int half = gridDim.x >> 1;
    const float* A; const float* W; const float* bias;
    int row0;
    if (blockIdx.x < half) { A = A0; W = W0; bias = b0; row0 = blockIdx.x << 7; }
    else                   { A = A1; W = W1; bias = b1; row0 = (blockIdx.x - half) << 7; }
    const int bn = blockIdx.y << 6;
    const int crow0 = blockIdx.x << 7;

    // staging maps
    const int wk  = tid >> 3;            // 0..31 W k-row
    const int wg0 = tid & 7;             // W n-group (first half)

    float4 ra[4], rw0, rw1;

    // --- register load of chunk k0 ---
    auto load_regs = [&](int k0) {
        #pragma unroll
        for (int i = 0; i < 4; ++i) {
            int idx = tid + (i << 8);
            int row = idx >> 3, gr = idx & 7;
            ra[i] = *reinterpret_cast<const float4*>(A + (size_t)(row0 + row) * K + k0 + (gr << 2));
        }
        rw0 = *reinterpret_cast<const float4*>(W + (size_t)(k0 + wk) * HH + bn + (wg0 << 2));
        rw1 = *reinterpret_cast<const float4*>(W + (size_t)(k0 + wk) * HH + bn + ((wg0 + 8) << 2));
    };
    auto store_smem = [&](int s) {
        #pragma unroll
        for (int i = 0; i < 4; ++i) {
            int idx = tid + (i << 8);
            int row = idx >> 3, gr = idx & 7;
            int phys = gr ^ (row & 7);
            uint4 u;
            u.x = f2tf32(ra[i].x); u.y = f2tf32(ra[i].y);
            u.z = f2tf32(ra[i].z); u.w = f2tf32(ra[i].w);
            *reinterpret_cast<uint4*>(&As[s][(row << 5) + (phys << 2)]) = u;
        }
        {
            int p0 = wg0 ^ ((wk & 3) << 1);
            int p1 = (wg0 + 8) ^ ((wk & 3) << 1);
            uint4 u0, u1;
            u0.x = f2tf32(rw0.x); u0.y = f2tf32(rw0.y); u0.z = f2tf32(rw0.z); u0.w = f2tf32(rw0.w);
            u1.x = f2tf32(rw1.x); u1.y = f2tf32(rw1.y); u1.z = f2tf32(rw1.z); u1.w = f2tf32(rw1.w);
            *reinterpret_cast<uint4*>(&Ws[s][(wk << 6) + (p0 << 2)]) = u0;
            *reinterpret_cast<uint4*>(&Ws[s][(wk << 6) + (p1 << 2)]) = u1;
        }
    };

    float acc[2][4][4] = {};   // [mf][nf][c]

    auto compute = [&](int s) {
        const unsigned* Ab = As[s];
        const unsigned* Wb = Ws[s];
        #pragma unroll
        for (int k8 = 0; k8 < 4; ++k8) {
            const int kg0 = k8 << 1;
            unsigned fa[2][4];
            #pragma unroll
            for (int mf = 0; mf < 2; ++mf) {
                int r0 = (wm << 5) + (mf << 4) + g;
                int r1 = r0 + 8;
                fa[mf][0] = Ab[(r0 << 5) + ((kg0 ^ (r0 & 7)) << 2) + tig];
                fa[mf][1] = Ab[(r1 << 5) + ((kg0 ^ (r1 & 7)) << 2) + tig];
                fa[mf][2] = Ab[(r0 << 5) + (((kg0 + 1) ^ (r0 & 7)) << 2) + tig];
                fa[mf][3] = Ab[(r1 << 5) + (((kg0 + 1) ^ (r1 & 7)) << 2) + tig];
            }
            const int krow0 = (k8 << 3) + tig;
            const int krow1 = krow0 + 4;
            const int f0 = tig << 1;
            #pragma unroll
            for (int nf = 0; nf < 4; ++nf) {
                int n  = (wn << 5) + (nf << 3) + g;
                int ng = n >> 2, nl = n & 3;
                unsigned fb0 = Wb[(krow0 << 6) + ((ng ^ f0) << 2) + nl];
                unsigned fb1 = Wb[(krow1 << 6) + ((ng ^ f0) << 2) + nl];
                MMA_TF32(acc[0][nf], fa[0][0], fa[0][1], fa[0][2], fa[0][3], fb0, fb1);
                MMA_TF32(acc[1][nf], fa[1][0], fa[1][1], fa[1][2], fa[1][3], fb0, fb1);
            }
        }
    };

    const int nk = K >> 5;
    load_regs(0);
    store_smem(0);
    __syncthreads();

    int cur = 0;
    for (int t = 1; t <= nk; ++t) {
        const bool hn = (t < nk);
        if (hn) load_regs(t << 5);
        compute(cur);
        if (hn) {
            const int nxt = cur ^ 1;
            store_smem(nxt);
            __syncthreads();
            cur = nxt;
        }
    }

    // epilogue
    #pragma unroll
    for (int mf = 0; mf < 2; ++mf) {
        #pragma unroll
        for (int nf = 0; nf < 4; ++nf) {
            const int col = bn + (wn << 5) + (nf << 3) + (tig << 1);
            float bx = 0.f, by = 0.f;
            if (bias) { bx = bias[col]; by = bias[col + 1]; }
            const int r0 = crow0 + (wm << 5) + (mf << 4) + g;
            const int r1 = r0 + 8;
            float v0 = acc[mf][nf][0] + bx, v1 = acc[mf][nf][1] + by;
            float v2 = acc[mf][nf][2] + bx, v3 = acc[mf][nf][3] + by;
            if (do_relu) {
                v0 = fmaxf(v0, 0.f); v1 = fmaxf(v1, 0.f);
                v2 = fmaxf(v2, 0.f); v3 = fmaxf(v3, 0.f);
            }
            float2 o01; o01.x = v0; o01.y = v1;
            float2 o23; o23.x = v2; o23.y = v3;
            *reinterpret_cast<float2*>(C + (size_t)r0 * HH + col) = o01;
            *reinterpret_cast<float2*>(C + (size_t)r1 * HH + col) = o23;
        }
    }
}

// ---------------- per-row dots: out[row] = sum_h M[row,h] * w[h] ----------------
__global__ __launch_bounds__(256) void row_dots(
    const float* __restrict__ Mx, const float* __restrict__ w, float* __restrict__ outd)
{
    const int row  = (blockIdx.x << 3) + (threadIdx.x >> 5);
    const int lane = threadIdx.x & 31;
    const float* r = Mx + (size_t)row * HH + (lane << 3);
    float4 x0 = *reinterpret_cast<const float4*>(r);
    float4 x1 = *reinterpret_cast<const float4*>(r + 4);
    const float* wp = w + (lane << 3);
    float4 w0 = *reinterpret_cast<const float4*>(wp);
    float4 w1 = *reinterpret_cast<const float4*>(wp + 4);
    float d = x0.x*w0.x + x0.y*w0.y + x0.z*w0.z + x0.w*w0.w
            + x1.x*w1.x + x1.y*w1.y + x1.z*w1.z + x1.w*w1.w;
    #pragma unroll
    for (int o = 16; o; o >>= 1) d += __shfl_down_sync(0xffffffffu, d, o);
    if (lane == 0) outd[row] = d;
}

// ---------------- packed-f32x2 pairwise abs kernel ----------------
// out[b,i,j] = sigmoid( 0.5*(da_i + dc_j + sum_h |a_i,h + c_j,h| * w_h) + b2 )
// block tile 64i x 32j, thread: 8 i (as 4 f32x2 pairs) x 1 j.
#define ADD2(d,a,b)   asm("add.rn.f32x2 %0,%1,%2;"     : "=l"(d) : "l"(a), "l"(b))
#define FMA2(d,a,b,c) asm("fma.rn.f32x2 %0,%1,%2,%3;"  : "=l"(d) : "l"(a), "l"(b), "l"(c))
#define ABS_MASK 0x7FFFFFFF7FFFFFFFULL

__global__ __launch_bounds__(256) void pair_abs_kernel(
    const float* __restrict__ Aa, const float* __restrict__ Cc,
    const float* __restrict__ da, const float* __restrict__ dc,
    const float* __restrict__ w2, const float* __restrict__ b2p,
    float* __restrict__ out)
{
    __shared__ float  aS[2][32][64];   // [h][i]
    __shared__ float  cD[2][32][64];   // [h][2j] duplicated (c,c)
    __shared__ float2 wD[HH];          // (w,w)

    const int tid = threadIdx.x;
    const int tx  = tid & 31;          // j
    const int ty  = tid >> 5;          // 0..7 -> i groups {4ty..4ty+3, 32+4ty..}
    const int i0  = blockIdx.x << 6, j0 = blockIdx.y << 5;
    const int b   = blockIdx.z;
    { float w = w2[tid]; wD[tid] = make_float2(w, w); }

    // staging maps
    const int aRow = tid >> 2;         // 0..63
    const int ah   = (tid & 3) << 3;   // 0,8,16,24
    const int cRow = tid >> 3;         // 0..31
    const int ch   = (tid & 7) << 2;   // 0..28

    const float* Ab = Aa + ((size_t)b * NNODE + i0) * HH;
    const float* Cb = Cc + ((size_t)b * NNODE + j0) * HH;

    ull acc0 = 0, acc1 = 0, acc2 = 0, acc3 = 0;

    float4 av0, av1, cv;
    auto load_regs = [&](int h0) {
        const float* ap = Ab + (size_t)aRow * HH + h0 + ah;
        const float* cp = Cb + (size_t)cRow * HH + h0 + ch;
        av0 = *reinterpret_cast<const float4*>(ap);
        av1 = *reinterpret_cast<const float4*>(ap + 4);
        cv  = *reinterpret_cast<const float4*>(cp);
    };
    auto store_smem = [&](int s) {
        aS[s][ah+0][aRow]=av0.x; aS[s][ah+1][aRow]=av0.y; aS[s][ah+2][aRow]=av0.z; aS[s][ah+3][aRow]=av0.w;
        aS[s][ah+4][aRow]=av1.x; aS[s][ah+5][aRow]=av1.y; aS[s][ah+6][aRow]=av1.z; aS[s][ah+7][aRow]=av1.w;
        *reinterpret_cast<float2*>(&cD[s][ch+0][cRow<<1]) = make_float2(cv.x, cv.x);
        *reinterpret_cast<float2*>(&cD[s][ch+1][cRow<<1]) = make_float2(cv.y, cv.y);
        *reinterpret_cast<float2*>(&cD[s][ch+2][cRow<<1]) = make_float2(cv.z, cv.z);
        *reinterpret_cast<float2*>(&cD[s][ch+3][cRow<<1]) = make_float2(cv.w, cv.w);
    };

    load_regs(0);
    store_smem(0);
    __syncthreads();

    int cur = 0;
    for (int t = 1; t <= 8; ++t) {
        const bool hn = (t < 8);
        if (hn) load_regs(t << 5);
        const int hb = (t - 1) << 5;
        #pragma unroll
        for (int h = 0; h < 32; ++h) {
            ulonglong2 pa = *reinterpret_cast<const ulonglong2*>(&aS[cur][h][ty << 2]);
            ulonglong2 pb = *reinterpret_cast<const ulonglong2*>(&aS[cur][h][32 + (ty << 2)]);
            ull c2  = *reinterpret_cast<const ull*>(&cD[cur][h][tx << 1]);
            ull wp  = *reinterpret_cast<const ull*>(&wD[hb + h]);
            ull t0, t1, t2, t3;
            ADD2(t0, pa.x, c2); t0 &= ABS_MASK; FMA2(acc0, t0, wp, acc0);
            ADD2(t1, pa.y, c2); t1 &= ABS_MASK; FMA2(acc1, t1, wp, acc1);
            ADD2(t2, pb.x, c2); t2 &= ABS_MASK; FMA2(acc2, t2, wp, acc2);
            ADD2(t3, pb.y, c2); t3 &= ABS_MASK; FMA2(acc3, t3, wp, acc3);
        }
        if (hn) {
            const int nxt = cur ^ 1;
            store_smem(nxt);
            __syncthreads();
            cur = nxt;
        }
    }

    const float b2v = b2p[0];
    const float dcj = dc[(size_t)b * NNODE + j0 + tx];
    float r[8];
    r[0] = __uint_as_float((unsigned)(acc0 & 0xffffffffu));
    r[1] = __uint_as_float((unsigned)(acc0 >> 32));
    r[2] = __uint_as_float((unsigned)(acc1 & 0xffffffffu));
    r[3] = __uint_as_float((unsigned)(acc1 >> 32));
    r[4] = __uint_as_float((unsigned)(acc2 & 0xffffffffu));
    r[5] = __uint_as_float((unsigned)(acc2 >> 32));
    r[6] = __uint_as_float((unsigned)(acc3 & 0xffffffffu));
    r[7] = __uint_as_float((unsigned)(acc3 >> 32));
    #pragma unroll
    for (int q = 0; q < 8; ++q) {
        const int i = ((q < 4) ? (ty << 2) + q : 32 + (ty << 2) + (q - 4));
        const float dai = da[(size_t)b * NNODE + i0 + i];
        const float s = 0.5f * (dai + dcj + r[q]) + b2v;
        out[((size_t)b * NNODE + i0 + i) * NNODE + j0 + tx] = 1.f / (1.f + __expf(-s));
    }
}

// ---------------- invariance reduction ----------------
__global__ __launch_bounds__(256) void reduce_stage1(const float* __restrict__ causal)
{
    const int p = blockIdx.x * 256 + threadIdx.x;
    float x[8];
    #pragma unroll
    for (int b = 0; b < 8; ++b) x[b] = causal[b * NMAT + p];
    float stab = 0.f, s = 0.f;
    #pragma unroll
    for (int b = 0; b < 8; ++b) { stab += fabsf(x[b] - x[(b + 7) & 7]); s += x[b]; }
    const float m = s * 0.125f;
    float var = 0.f;
    #pragma unroll
    for (int b = 0; b < 8; ++b) { float d = x[b] - m; var = fmaf(d, d, var); }
    float sd = sqrtf(var * (1.f / 7.f));

    #pragma unroll
    for (int o = 16; o; o >>= 1) {
        stab += __shfl_down_sync(0xffffffffu, stab, o);
        sd   += __shfl_down_sync(0xffffffffu, sd, o);
    }
    __shared__ float sm[8][2];
    const int wid = threadIdx.x >> 5, lane = threadIdx.x & 31;
    if (lane == 0) { sm[wid][0] = stab; sm[wid][1] = sd; }
    __syncthreads();
    if (threadIdx.x == 0) {
        float a = 0.f, c = 0.f;
        #pragma unroll
        for (int w = 0; w < 8; ++w) { a += sm[w][0]; c += sm[w][1]; }
        g_partial[blockIdx.x * 2 + 0] = a;
        g_partial[blockIdx.x * 2 + 1] = c;
    }
}

__global__ __launch_bounds__(256) void reduce_stage2(float* __restrict__ inv)
{
    float a = g_partial[threadIdx.x * 2 + 0];
    float c = g_partial[threadIdx.x * 2 + 1];
    #pragma unroll
    for (int o = 16; o; o >>= 1) {
        a += __shfl_down_sync(0xffffffffu, a, o);
        c += __shfl_down_sync(0xffffffffu, c, o);
    }
    __shared__ float sm[8][2];
    const int wid = threadIdx.x >> 5, lane = threadIdx.x & 31;
    if (lane == 0) { sm[wid][0] = a; sm[wid][1] = c; }
    __syncthreads();
    if (threadIdx.x == 0) {
        float sa = 0.f, sc = 0.f;
        #pragma unroll
        for (int w = 0; w < 8; ++w) { sa += sm[w][0]; sc += sm[w][1]; }
        const float stability   = sa / (8.f * 65536.f);
        const float consistency = sc / 65536.f;
        inv[0] = 1.f - (stability + consistency) * 0.5f;
    }
}

// ---------------- launch ----------------
extern "C" void kernel_launch(void* const* d_in, const int* in_sizes, int n_in,
                              void* d_out, int out_size)
{
    const float* img    = (const float*)d_in[0];
    const float* txt    = (const float*)d_in[1];
    const float* ft_W1  = (const float*)d_in[2];
    const float* ft_b1  = (const float*)d_in[3];
    const float* ft_W2  = (const float*)d_in[4];
    const float* ft_b2  = (const float*)d_in[5];
    const float* sl_W1a = (const float*)d_in[6];
    const float* sl_W1b = (const float*)d_in[7];
    const float* sl_b1  = (const float*)d_in[8];
    const float* sl_W2  = (const float*)d_in[9];
    const float* sl_b2  = (const float*)d_in[10];
    const float* cn_W1a = (const float*)d_in[11];
    const float* cn_W1b = (const float*)d_in[12];
    const float* cn_b1  = (const float*)d_in[13];
    const float* cn_W2  = (const float*)d_in[14];
    const float* cn_b2  = (const float*)d_in[15];

    float* outp      = (float*)d_out;
    float* structure = outp;
    float* causal    = outp + OUT_MAT;
    float* inv       = outp + 2 * OUT_MAT;

    float *x1, *h, *ac, *dots;
    cudaGetSymbolAddress((void**)&x1,   g_x1);
    cudaGetSymbolAddress((void**)&h,    g_h);
    cudaGetSymbolAddress((void**)&ac,   g_ac);
    cudaGetSymbolAddress((void**)&dots, g_dots);

    const dim3 gemm_grid(M2 / 128, HH / 64);            // 32 x 4 = 128 blocks
    const dim3 pair_grid(NNODE / 64, NNODE / 32, BB);   // 4 x 8 x 8 = 256 blocks

    gemm2_tc<<<gemm_grid, 256>>>(img, txt, ft_W1, ft_W1, ft_b1, ft_b1, x1, FF, 1);
    gemm2_tc<<<gemm_grid, 256>>>(x1, x1 + (size_t)MM * HH, ft_W2, ft_W2, ft_b2, ft_b2, h, HH, 0);
    gemm2_tc<<<gemm_grid, 256>>>(h, h + (size_t)MM * HH, sl_W1a, sl_W1b, sl_b1, nullptr, ac, HH, 0);
    row_dots<<<M2 / 8, 256>>>(ac, sl_W2, dots);
    pair_abs_kernel<<<pair_grid, 256>>>(ac, ac + (size_t)MM * HH, dots, dots + MM,
                                        sl_W2, sl_b2, structure);
    gemm2_tc<<<gemm_grid, 256>>>(structure, structure, cn_W1a, cn_W1b, cn_b1, nullptr, ac, HH, 0);
    row_dots<<<M2 / 8, 256>>>(ac, cn_W2, dots);
    pair_abs_kernel<<<pair_grid, 256>>>(ac, ac + (size_t)MM * HH, dots, dots + MM,
                                        cn_W2, cn_b2, causal);
    reduce_stage1<<<256, 256>>>(causal);
    reduce_stage2<<<1, 256>>>(inv);
}

// round 6
// speedup vs baseline: 2.0300x; 1.1543x over previous
#include <cuda_runtime.h>
#include <math.h>

#define BB 8
#define NNODE 256
#define FF 512
#define HH 256
#define MM 2048
#define M2 4096
#define NMAT 65536
#define OUT_MAT 524288

typedef unsigned u32;
typedef unsigned long long ull;

// ---------------- scratch ----------------
__device__ float g_x1[M2*HH];
__device__ float g_h [M2*HH];
__device__ float g_ac[M2*HH];
__device__ float g_partial[2*256];
__device__ u32  g_cnt;

__device__ __forceinline__ u32 pack_bf16(float lo, float hi) {
    u32 d; asm("cvt.rn.bf16x2.f32 %0, %1, %2;" : "=r"(d) : "f"(hi), "f"(lo)); return d;
}
__device__ __forceinline__ u32 smaddr(const void* p) {
    u32 a;
    asm("{.reg .u64 t; cvta.to.shared.u64 t, %1; cvt.u32.u64 %0, t;}" : "=r"(a) : "l"(p));
    return a;
}
#define LDSM4(r0,r1,r2,r3,a) \
    asm volatile("ldmatrix.sync.aligned.m8n8.x4.shared.b16 {%0,%1,%2,%3}, [%4];" \
        : "=r"(r0),"=r"(r1),"=r"(r2),"=r"(r3) : "r"(a))
#define LDSM4T(r0,r1,r2,r3,a) \
    asm volatile("ldmatrix.sync.aligned.m8n8.x4.trans.shared.b16 {%0,%1,%2,%3}, [%4];" \
        : "=r"(r0),"=r"(r1),"=r"(r2),"=r"(r3) : "r"(a))
#define MMA_BF16(acc,a0,a1,a2,a3,b0,b1) \
    asm volatile("mma.sync.aligned.m16n8k16.row.col.f32.bf16.bf16.f32 " \
        "{%0,%1,%2,%3}, {%4,%5,%6,%7}, {%8,%9}, {%0,%1,%2,%3};" \
        : "+f"((acc)[0]),"+f"((acc)[1]),"+f"((acc)[2]),"+f"((acc)[3]) \
        : "r"(a0),"r"(a1),"r"(a2),"r"(a3),"r"(b0),"r"(b1))

// ---------------- bf16 tensor-core batched GEMM ----------------
// rows [0,2048): C = act(A0 @ W0 + b0); rows [2048,4096): act(A1 @ W1 + b1)
// 128x64 block tile, 8 warps (4m x 2n), warp tile 32x32, K chunked by 32.
// A smem [row][k] bf16 (64B rows, swizzle pg = kg ^ ((row>>1)&3)).
// W smem [k][n]  bf16 (128B rows, swizzle pg = ng ^ (k&7)).
__global__ __launch_bounds__(256) void gemm2_bf16(
    const float* __restrict__ A0, const float* __restrict__ A1,
    const float* __restrict__ W0, const float* __restrict__ W1,
    const float* __restrict__ b0, const float* __restrict__ b1,
    float* __restrict__ C, int K, int do_relu)
{
    __shared__ __align__(16) u32 AsU[2][2048];  // 128 rows * 4 grp * 4 u32 (8KB/stage)
    __shared__ __align__(16) u32 WsU[2][1024];  // 32 k * 8 grp * 4 u32 (4KB/stage)

    const int tid = threadIdx.x;
    const int warp = tid >> 5, lane = tid & 31;
    const int g   = lane >> 2;           // 0..7
    const int tig = lane & 3;            // 0..3
    const int wm  = warp >> 1;           // 0..3
    const int wn  = warp & 1;            // 0..1

    const int half = gridDim.x >> 1;
    const float* A; const float* W; const float* bias;
    int row0;
    if (blockIdx.x < half) { A = A0; W = W0; bias = b0; row0 = blockIdx.x << 7; }
    else                   { A = A1; W = W1; bias = b1; row0 = (blockIdx.x - half) << 7; }
    const int bn = blockIdx.y << 6;
    const int crow0 = blockIdx.x << 7;

    // staging maps
    const int wk  = tid >> 3;            // 0..31 W k-row
    const int wg  = tid & 7;             // W n-group

    float4 ra0[2], ra1[2], rw0, rw1;
    auto load_regs = [&](int k0) {
        #pragma unroll
        for (int i = 0; i < 2; ++i) {
            int gi = tid + (i << 8);
            int row = gi >> 2, kg = gi & 3;
            const float* ap = A + (size_t)(row0 + row) * K + k0 + (kg << 3);
            ra0[i] = *reinterpret_cast<const float4*>(ap);
            ra1[i] = *reinterpret_cast<const float4*>(ap + 4);
        }
        const float* wp = W + (size_t)(k0 + wk) * HH + bn + (wg << 3);
        rw0 = *reinterpret_cast<const float4*>(wp);
        rw1 = *reinterpret_cast<const float4*>(wp + 4);
    };
    auto store_smem = [&](int s) {
        #pragma unroll
        for (int i = 0; i < 2; ++i) {
            int gi = tid + (i << 8);
            int row = gi >> 2, kg = gi & 3;
            int pg = kg ^ ((row >> 1) & 3);
            uint4 u;
            u.x = pack_bf16(ra0[i].x, ra0[i].y);
            u.y = pack_bf16(ra0[i].z, ra0[i].w);
            u.z = pack_bf16(ra1[i].x, ra1[i].y);
            u.w = pack_bf16(ra1[i].z, ra1[i].w);
            *reinterpret_cast<uint4*>(&AsU[s][(row << 4) + (pg << 2)]) = u;
        }
        {
            int pg = wg ^ (wk & 7);
            uint4 u;
            u.x = pack_bf16(rw0.x, rw0.y);
            u.y = pack_bf16(rw0.z, rw0.w);
            u.z = pack_bf16(rw1.x, rw1.y);
            u.w = pack_bf16(rw1.z, rw1.w);
            *reinterpret_cast<uint4*>(&WsU[s][(wk << 5) + (pg << 2)]) = u;
        }
    };

    // ldmatrix base addresses (per-lane, stage 0)
    const int hi   = lane >> 4;
    const int rowL = (wm << 5) + (lane & 15);
    const int sA   = (rowL >> 1) & 3;
    const u32 aB0  = smaddr(&AsU[0][0]) + rowL * 64 + ((hi ^ sA) << 4);
    const int kL   = lane & 15;
    const int sB   = lane & 7;
    const int ng0  = (wn << 2) + hi;
    const u32 bB0  = smaddr(&WsU[0][0]) + kL * 128 + ((ng0 ^ sB) << 4);

    float acc[2][4][4] = {};

    auto compute = [&](int s) {
        const u32 aOff = (u32)(s * 8192);
        const u32 wOff = (u32)(s * 4096);
        #pragma unroll
        for (int kb = 0; kb < 2; ++kb) {
            const u32 ax = (aB0 ^ (kb << 5)) + aOff;      // k16 block: pg ^ 2
            const u32 bx = bB0 + wOff + (kb << 11);        // +2048 bytes for k16 block
            u32 a0[4], a1[4];
            LDSM4(a0[0], a0[1], a0[2], a0[3], ax);         // mf=0
            LDSM4(a1[0], a1[1], a1[2], a1[3], ax + 1024);  // mf=1 (+16 rows * 64B)
            #pragma unroll
            for (int nf16 = 0; nf16 < 2; ++nf16) {
                u32 b[4];
                LDSM4T(b[0], b[1], b[2], b[3], bx ^ (nf16 << 5));  // ng ^ 2
                const int nfa = nf16 << 1;
                MMA_BF16(acc[0][nfa + 0], a0[0], a0[1], a0[2], a0[3], b[0], b[1]);
                MMA_BF16(acc[1][nfa + 0], a1[0], a1[1], a1[2], a1[3], b[0], b[1]);
                MMA_BF16(acc[0][nfa + 1], a0[0], a0[1], a0[2], a0[3], b[2], b[3]);
                MMA_BF16(acc[1][nfa + 1], a1[0], a1[1], a1[2], a1[3], b[2], b[3]);
            }
        }
    };

    const int nk = K >> 5;
    load_regs(0);
    store_smem(0);
    __syncthreads();

    int cur = 0;
    for (int t = 1; t <= nk; ++t) {
        const bool hn = (t < nk);
        if (hn) load_regs(t << 5);
        compute(cur);
        if (hn) {
            const int nxt = cur ^ 1;
            store_smem(nxt);
            __syncthreads();
            cur = nxt;
        }
    }

    // epilogue
    #pragma unroll
    for (int mf = 0; mf < 2; ++mf) {
        #pragma unroll
        for (int nf = 0; nf < 4; ++nf) {
            const int col = bn + (wn << 5) + (nf << 3) + (tig << 1);
            float bx = 0.f, by = 0.f;
            if (bias) { bx = bias[col]; by = bias[col + 1]; }
            const int r0 = crow0 + (wm << 5) + (mf << 4) + g;
            const int r1 = r0 + 8;
            float v0 = acc[mf][nf][0] + bx, v1 = acc[mf][nf][1] + by;
            float v2 = acc[mf][nf][2] + bx, v3 = acc[mf][nf][3] + by;
            if (do_relu) {
                v0 = fmaxf(v0, 0.f); v1 = fmaxf(v1, 0.f);
                v2 = fmaxf(v2, 0.f); v3 = fmaxf(v3, 0.f);
            }
            float2 o01; o01.x = v0; o01.y = v1;
            float2 o23; o23.x = v2; o23.y = v3;
            *reinterpret_cast<float2*>(C + (size_t)r0 * HH + col) = o01;
            *reinterpret_cast<float2*>(C + (size_t)r1 * HH + col) = o23;
        }
    }
}

// ---------------- packed-f32x2 pairwise abs kernel with fused row dots ------
// out[b,i,j] = sigmoid( 0.5*(da_i + dc_j + sum_h |a_i,h + c_j,h| w_h) + b2 )
#define ADD2(d,a,b)   asm("add.rn.f32x2 %0,%1,%2;"     : "=l"(d) : "l"(a), "l"(b))
#define FMA2(d,a,b,c) asm("fma.rn.f32x2 %0,%1,%2,%3;"  : "=l"(d) : "l"(a), "l"(b), "l"(c))
#define ABS_MASK 0x7FFFFFFF7FFFFFFFULL

__global__ __launch_bounds__(256) void pair_abs_kernel(
    const float* __restrict__ Aa, const float* __restrict__ Cc,
    const float* __restrict__ w2, const float* __restrict__ b2p,
    float* __restrict__ out)
{
    __shared__ float  aS[2][32][64];   // [h][i]
    __shared__ float  cD[2][32][64];   // [h][2j] duplicated (c,c)
    __shared__ float2 wD[HH];          // (w,w)
    __shared__ float  daS[64], dcS[32];

    const int tid = threadIdx.x;
    const int tx  = tid & 31;          // j
    const int ty  = tid >> 5;          // 0..7
    const int i0  = blockIdx.x << 6, j0 = blockIdx.y << 5;
    const int b   = blockIdx.z;
    { float w = w2[tid]; wD[tid] = make_float2(w, w); }

    const int aRow = tid >> 2;         // 0..63
    const int ah   = (tid & 3) << 3;   // 0,8,16,24
    const int cRow = tid >> 3;         // 0..31
    const int ch   = (tid & 7) << 2;   // 0..28

    const float* Ab = Aa + ((size_t)b * NNODE + i0) * HH;
    const float* Cb = Cc + ((size_t)b * NNODE + j0) * HH;

    ull acc0 = 0, acc1 = 0, acc2 = 0, acc3 = 0;
    float pa_dot = 0.f, pc_dot = 0.f;

    float4 av0, av1, cv;
    auto load_regs = [&](int h0) {
        const float* ap = Ab + (size_t)aRow * HH + h0 + ah;
        const float* cp = Cb + (size_t)cRow * HH + h0 + ch;
        av0 = *reinterpret_cast<const float4*>(ap);
        av1 = *reinterpret_cast<const float4*>(ap + 4);
        cv  = *reinterpret_cast<const float4*>(cp);
    };
    auto store_smem = [&](int s, int h0) {
        aS[s][ah+0][aRow]=av0.x; aS[s][ah+1][aRow]=av0.y; aS[s][ah+2][aRow]=av0.z; aS[s][ah+3][aRow]=av0.w;
        aS[s][ah+4][aRow]=av1.x; aS[s][ah+5][aRow]=av1.y; aS[s][ah+6][aRow]=av1.z; aS[s][ah+7][aRow]=av1.w;
        *reinterpret_cast<float2*>(&cD[s][ch+0][cRow<<1]) = make_float2(cv.x, cv.x);
        *reinterpret_cast<float2*>(&cD[s][ch+1][cRow<<1]) = make_float2(cv.y, cv.y);
        *reinterpret_cast<float2*>(&cD[s][ch+2][cRow<<1]) = make_float2(cv.z, cv.z);
        *reinterpret_cast<float2*>(&cD[s][ch+3][cRow<<1]) = make_float2(cv.w, cv.w);
        // fused separable dots
        pa_dot += av0.x*wD[h0+ah+0].x + av0.y*wD[h0+ah+1].x
                + av0.z*wD[h0+ah+2].x + av0.w*wD[h0+ah+3].x
                + av1.x*wD[h0+ah+4].x + av1.y*wD[h0+ah+5].x
                + av1.z*wD[h0+ah+6].x + av1.w*wD[h0+ah+7].x;
        pc_dot += cv.x*wD[h0+ch+0].x + cv.y*wD[h0+ch+1].x
                + cv.z*wD[h0+ch+2].x + cv.w*wD[h0+ch+3].x;
    };

    load_regs(0);
    __syncthreads();          // wD visible
    store_smem(0, 0);
    __syncthreads();

    int cur = 0;
    for (int t = 1; t <= 8; ++t) {
        const bool hn = (t < 8);
        if (hn) load_regs(t << 5);
        #pragma unroll
        for (int h = 0; h < 32; ++h) {
            ulonglong2 pa = *reinterpret_cast<const ulonglong2*>(&aS[cur][h][ty << 2]);
            ulonglong2 pb = *reinterpret_cast<const ulonglong2*>(&aS[cur][h][32 + (ty << 2)]);
            ull c2 = *reinterpret_cast<const ull*>(&cD[cur][h][tx << 1]);
            ull wp = *reinterpret_cast<const ull*>(&wD[((t - 1) << 5) + h]);
            ull t0, t1, t2, t3;
            ADD2(t0, pa.x, c2); t0 &= ABS_MASK; FMA2(acc0, t0, wp, acc0);
            ADD2(t1, pa.y, c2); t1 &= ABS_MASK; FMA2(acc1, t1, wp, acc1);
            ADD2(t2, pb.x, c2); t2 &= ABS_MASK; FMA2(acc2, t2, wp, acc2);
            ADD2(t3, pb.y, c2); t3 &= ABS_MASK; FMA2(acc3, t3, wp, acc3);
        }
        if (hn) {
            const int nxt = cur ^ 1;
            store_smem(nxt, t << 5);
            __syncthreads();
            cur = nxt;
        }
    }

    // reduce fused dots (quad / octet shfl groups are lane-aligned)
    {
        float v = pa_dot;
        v += __shfl_xor_sync(0xffffffffu, v, 1);
        v += __shfl_xor_sync(0xffffffffu, v, 2);
        if ((tid & 3) == 0) daS[aRow] = v;
        float u = pc_dot;
        u += __shfl_xor_sync(0xffffffffu, u, 1);
        u += __shfl_xor_sync(0xffffffffu, u, 2);
        u += __shfl_xor_sync(0xffffffffu, u, 4);
        if ((tid & 7) == 0) dcS[cRow] = u;
    }
    __syncthreads();

    const float b2v = b2p[0];
    const float dcj = dcS[tx];
    float r[8];
    r[0] = __uint_as_float((u32)(acc0 & 0xffffffffu));
    r[1] = __uint_as_float((u32)(acc0 >> 32));
    r[2] = __uint_as_float((u32)(acc1 & 0xffffffffu));
    r[3] = __uint_as_float((u32)(acc1 >> 32));
    r[4] = __uint_as_float((u32)(acc2 & 0xffffffffu));
    r[5] = __uint_as_float((u32)(acc2 >> 32));
    r[6] = __uint_as_float((u32)(acc3 & 0xffffffffu));
    r[7] = __uint_as_float((u32)(acc3 >> 32));
    #pragma unroll
    for (int q = 0; q < 8; ++q) {
        const int i = ((q < 4) ? (ty << 2) + q : 32 + (ty << 2) + (q - 4));
        const float s = 0.5f * (daS[i] + dcj + r[q]) + b2v;
        out[((size_t)b * NNODE + i0 + i) * NNODE + j0 + tx] = 1.f / (1.f + __expf(-s));
    }
}

// ---------------- fused invariance reduction (single launch) ----------------
__global__ __launch_bounds__(256) void reduce_all(
    const float* __restrict__ causal, float* __restrict__ inv)
{
    const int p = blockIdx.x * 256 + threadIdx.x;
    float x[8];
    #pragma unroll
    for (int b = 0; b < 8; ++b) x[b] = causal[b * NMAT + p];
    float stab = 0.f, s = 0.f;
    #pragma unroll
    for (int b = 0; b < 8; ++b) { stab += fabsf(x[b] - x[(b + 7) & 7]); s += x[b]; }
    const float m = s * 0.125f;
    float var = 0.f;
    #pragma unroll
    for (int b = 0; b < 8; ++b) { float d = x[b] - m; var = fmaf(d, d, var); }
    float sd = sqrtf(var * (1.f / 7.f));   // ddof=1

    #pragma unroll
    for (int o = 16; o; o >>= 1) {
        stab += __shfl_down_sync(0xffffffffu, stab, o);
        sd   += __shfl_down_sync(0xffffffffu, sd, o);
    }
    __shared__ float sm[8][2];
    const int wid = threadIdx.x >> 5, lane = threadIdx.x & 31;
    if (lane == 0) { sm[wid][0] = stab; sm[wid][1] = sd; }
    __syncthreads();
    if (threadIdx.x == 0) {
        float a = 0.f, c = 0.f;
        #pragma unroll
        for (int w = 0; w < 8; ++w) { a += sm[w][0]; c += sm[w][1]; }
        g_partial[blockIdx.x * 2 + 0] = a;
        g_partial[blockIdx.x * 2 + 1] = c;
    }

    // last-block finalization
    __shared__ int isLast;
    __threadfence();
    if (threadIdx.x == 0) {
        u32 cdone = atomicAdd(&g_cnt, 1u);
        isLast = (cdone == 255u) ? 1 : 0;
    }
    __syncthreads();
    if (isLast) {
        float a = g_partial[threadIdx.x * 2 + 0];
        float c = g_partial[threadIdx.x * 2 + 1];
        #pragma unroll
        for (int o = 16; o; o >>= 1) {
            a += __shfl_down_sync(0xffffffffu, a, o);
            c += __shfl_down_sync(0xffffffffu, c, o);
        }
        if (lane == 0) { sm[wid][0] = a; sm[wid][1] = c; }
        __syncthreads();
        if (threadIdx.x == 0) {
            float sa = 0.f, sc = 0.f;
            #pragma unroll
            for (int w = 0; w < 8; ++w) { sa += sm[w][0]; sc += sm[w][1]; }
            const float stability   = sa / (8.f * 65536.f);
            const float consistency = sc / 65536.f;
            inv[0] = 1.f - (stability + consistency) * 0.5f;
            g_cnt = 0u;   // reset for next graph replay
        }
    }
}

// ---------------- launch ----------------
extern "C" void kernel_launch(void* const* d_in, const int* in_sizes, int n_in,
                              void* d_out, int out_size)
{
    const float* img    = (const float*)d_in[0];
    const float* txt    = (const float*)d_in[1];
    const float* ft_W1  = (const float*)d_in[2];
    const float* ft_b1  = (const float*)d_in[3];
    const float* ft_W2  = (const float*)d_in[4];
    const float* ft_b2  = (const float*)d_in[5];
    const float* sl_W1a = (const float*)d_in[6];
    const float* sl_W1b = (const float*)d_in[7];
    const float* sl_b1  = (const float*)d_in[8];
    const float* sl_W2  = (const float*)d_in[9];
    const float* sl_b2  = (const float*)d_in[10];
    const float* cn_W1a = (const float*)d_in[11];
    const float* cn_W1b = (const float*)d_in[12];
    const float* cn_b1  = (const float*)d_in[13];
    const float* cn_W2  = (const float*)d_in[14];
    const float* cn_b2  = (const float*)d_in[15];

    float* outp      = (float*)d_out;
    float* structure = outp;
    float* causal    = outp + OUT_MAT;
    float* inv       = outp + 2 * OUT_MAT;

    float *x1, *h, *ac;
    cudaGetSymbolAddress((void**)&x1, g_x1);
    cudaGetSymbolAddress((void**)&h,  g_h);
    cudaGetSymbolAddress((void**)&ac, g_ac);

    const dim3 gemm_grid(M2 / 128, HH / 64);            // 32 x 4 = 128 blocks
    const dim3 pair_grid(NNODE / 64, NNODE / 32, BB);   // 4 x 8 x 8 = 256 blocks

    gemm2_bf16<<<gemm_grid, 256>>>(img, txt, ft_W1, ft_W1, ft_b1, ft_b1, x1, FF, 1);
    gemm2_bf16<<<gemm_grid, 256>>>(x1, x1 + (size_t)MM * HH, ft_W2, ft_W2, ft_b2, ft_b2, h, HH, 0);
    gemm2_bf16<<<gemm_grid, 256>>>(h, h + (size_t)MM * HH, sl_W1a, sl_W1b, sl_b1, nullptr, ac, HH, 0);
    pair_abs_kernel<<<pair_grid, 256>>>(ac, ac + (size_t)MM * HH, sl_W2, sl_b2, structure);
    gemm2_bf16<<<gemm_grid, 256>>>(structure, structure, cn_W1a, cn_W1b, cn_b1, nullptr, ac, HH, 0);
    pair_abs_kernel<<<pair_grid, 256>>>(ac, ac + (size_t)MM * HH, cn_W2, cn_b2, causal);
    reduce_all<<<256, 256>>>(causal, inv);
}

// round 8
// speedup vs baseline: 2.0757x; 1.0225x over previous
#include <cuda_runtime.h>
#include <math.h>

#define BB 8
#define NNODE 256
#define FF 512
#define HH 256
#define MM 2048
#define M2 4096
#define NMAT 65536
#define OUT_MAT 524288

typedef unsigned u32;
typedef unsigned long long ull;

// ---------------- scratch ----------------
__device__ float g_x1[M2*HH];
__device__ float g_h [M2*HH];
__device__ float g_ac[M2*HH];
__device__ float g_partial[2*256];
__device__ u32  g_cnt;

__device__ __forceinline__ u32 pack_bf16(float lo, float hi) {
    u32 d; asm("cvt.rn.bf16x2.f32 %0, %1, %2;" : "=r"(d) : "f"(hi), "f"(lo)); return d;
}
__device__ __forceinline__ u32 smaddr(const void* p) {
    u32 a;
    asm("{.reg .u64 t; cvta.to.shared.u64 t, %1; cvt.u32.u64 %0, t;}" : "=r"(a) : "l"(p));
    return a;
}
#define LDSM4(r0,r1,r2,r3,a) \
    asm volatile("ldmatrix.sync.aligned.m8n8.x4.shared.b16 {%0,%1,%2,%3}, [%4];" \
        : "=r"(r0),"=r"(r1),"=r"(r2),"=r"(r3) : "r"(a))
#define LDSM4T(r0,r1,r2,r3,a) \
    asm volatile("ldmatrix.sync.aligned.m8n8.x4.trans.shared.b16 {%0,%1,%2,%3}, [%4];" \
        : "=r"(r0),"=r"(r1),"=r"(r2),"=r"(r3) : "r"(a))
#define MMA_BF16(acc,a0,a1,a2,a3,b0,b1) \
    asm volatile("mma.sync.aligned.m16n8k16.row.col.f32.bf16.bf16.f32 " \
        "{%0,%1,%2,%3}, {%4,%5,%6,%7}, {%8,%9}, {%0,%1,%2,%3};" \
        : "+f"((acc)[0]),"+f"((acc)[1]),"+f"((acc)[2]),"+f"((acc)[3]) \
        : "r"(a0),"r"(a1),"r"(a2),"r"(a3),"r"(b0),"r"(b1))

// ---------------- bf16 tensor-core batched GEMM (unchanged, proven) ----------------
__global__ __launch_bounds__(256) void gemm2_bf16(
    const float* __restrict__ A0, const float* __restrict__ A1,
    const float* __restrict__ W0, const float* __restrict__ W1,
    const float* __restrict__ b0, const float* __restrict__ b1,
    float* __restrict__ C, int K, int do_relu)
{
    __shared__ __align__(16) u32 AsU[2][2048];
    __shared__ __align__(16) u32 WsU[2][1024];

    const int tid = threadIdx.x;
    const int warp = tid >> 5, lane = tid & 31;
    const int g   = lane >> 2;
    const int tig = lane & 3;
    const int wm  = warp >> 1;
    const int wn  = warp & 1;

    const int half = gridDim.x >> 1;
    const float* A; const float* W; const float* bias;
    int row0;
    if (blockIdx.x < half) { A = A0; W = W0; bias = b0; row0 = blockIdx.x << 7; }
    else                   { A = A1; W = W1; bias = b1; row0 = (blockIdx.x - half) << 7; }
    const int bn = blockIdx.y << 6;
    const int crow0 = blockIdx.x << 7;

    const int wk  = tid >> 3;
    const int wg  = tid & 7;

    float4 ra0[2], ra1[2], rw0, rw1;
    auto load_regs = [&](int k0) {
        #pragma unroll
        for (int i = 0; i < 2; ++i) {
            int gi = tid + (i << 8);
            int row = gi >> 2, kg = gi & 3;
            const float* ap = A + (size_t)(row0 + row) * K + k0 + (kg << 3);
            ra0[i] = *reinterpret_cast<const float4*>(ap);
            ra1[i] = *reinterpret_cast<const float4*>(ap + 4);
        }
        const float* wp = W + (size_t)(k0 + wk) * HH + bn + (wg << 3);
        rw0 = *reinterpret_cast<const float4*>(wp);
        rw1 = *reinterpret_cast<const float4*>(wp + 4);
    };
    auto store_smem = [&](int s) {
        #pragma unroll
        for (int i = 0; i < 2; ++i) {
            int gi = tid + (i << 8);
            int row = gi >> 2, kg = gi & 3;
            int pg = kg ^ ((row >> 1) & 3);
            uint4 u;
            u.x = pack_bf16(ra0[i].x, ra0[i].y);
            u.y = pack_bf16(ra0[i].z, ra0[i].w);
            u.z = pack_bf16(ra1[i].x, ra1[i].y);
            u.w = pack_bf16(ra1[i].z, ra1[i].w);
            *reinterpret_cast<uint4*>(&AsU[s][(row << 4) + (pg << 2)]) = u;
        }
        {
            int pg = wg ^ (wk & 7);
            uint4 u;
            u.x = pack_bf16(rw0.x, rw0.y);
            u.y = pack_bf16(rw0.z, rw0.w);
            u.z = pack_bf16(rw1.x, rw1.y);
            u.w = pack_bf16(rw1.z, rw1.w);
            *reinterpret_cast<uint4*>(&WsU[s][(wk << 5) + (pg << 2)]) = u;
        }
    };

    const int hi   = lane >> 4;
    const int rowL = (wm << 5) + (lane & 15);
    const int sA   = (rowL >> 1) & 3;
    const u32 aB0  = smaddr(&AsU[0][0]) + rowL * 64 + ((hi ^ sA) << 4);
    const int kL   = lane & 15;
    const int sB   = lane & 7;
    const int ng0  = (wn << 2) + hi;
    const u32 bB0  = smaddr(&WsU[0][0]) + kL * 128 + ((ng0 ^ sB) << 4);

    float acc[2][4][4] = {};

    auto compute = [&](int s) {
        const u32 aOff = (u32)(s * 8192);
        const u32 wOff = (u32)(s * 4096);
        #pragma unroll
        for (int kb = 0; kb < 2; ++kb) {
            const u32 ax = (aB0 ^ (kb << 5)) + aOff;
            const u32 bx = bB0 + wOff + (kb << 11);
            u32 a0[4], a1[4];
            LDSM4(a0[0], a0[1], a0[2], a0[3], ax);
            LDSM4(a1[0], a1[1], a1[2], a1[3], ax + 1024);
            #pragma unroll
            for (int nf16 = 0; nf16 < 2; ++nf16) {
                u32 b[4];
                LDSM4T(b[0], b[1], b[2], b[3], bx ^ (nf16 << 5));
                const int nfa = nf16 << 1;
                MMA_BF16(acc[0][nfa + 0], a0[0], a0[1], a0[2], a0[3], b[0], b[1]);
                MMA_BF16(acc[1][nfa + 0], a1[0], a1[1], a1[2], a1[3], b[0], b[1]);
                MMA_BF16(acc[0][nfa + 1], a0[0], a0[1], a0[2], a0[3], b[2], b[3]);
                MMA_BF16(acc[1][nfa + 1], a1[0], a1[1], a1[2], a1[3], b[2], b[3]);
            }
        }
    };

    const int nk = K >> 5;
    load_regs(0);
    store_smem(0);
    __syncthreads();

    int cur = 0;
    for (int t = 1; t <= nk; ++t) {
        const bool hn = (t < nk);
        if (hn) load_regs(t << 5);
        compute(cur);
        if (hn) {
            const int nxt = cur ^ 1;
            store_smem(nxt);
            __syncthreads();
            cur = nxt;
        }
    }

    #pragma unroll
    for (int mf = 0; mf < 2; ++mf) {
        #pragma unroll
        for (int nf = 0; nf < 4; ++nf) {
            const int col = bn + (wn << 5) + (nf << 3) + (tig << 1);
            float bx = 0.f, by = 0.f;
            if (bias) { bx = bias[col]; by = bias[col + 1]; }
            const int r0 = crow0 + (wm << 5) + (mf << 4) + g;
            const int r1 = r0 + 8;
            float v0 = acc[mf][nf][0] + bx, v1 = acc[mf][nf][1] + by;
            float v2 = acc[mf][nf][2] + bx, v3 = acc[mf][nf][3] + by;
            if (do_relu) {
                v0 = fmaxf(v0, 0.f); v1 = fmaxf(v1, 0.f);
                v2 = fmaxf(v2, 0.f); v3 = fmaxf(v3, 0.f);
            }
            float2 o01; o01.x = v0; o01.y = v1;
            float2 o23; o23.x = v2; o23.y = v3;
            *reinterpret_cast<float2*>(C + (size_t)r0 * HH + col) = o01;
            *reinterpret_cast<float2*>(C + (size_t)r1 * HH + col) = o23;
        }
    }
}

// ---------------- packed-f32x2 pairwise abs kernel, 512 threads ----------------
// out[b,i,j] = sigmoid( 0.5*(da_i + dc_j + sum_h |a_i,h + c_j,h| w_h) + b2 )
// block 64i x 64j, thread 4i(2 packed pairs) x 2j, grid 128 CTAs (1 wave).
#define ADD2(d,a,b)   asm("add.rn.f32x2 %0,%1,%2;"     : "=l"(d) : "l"(a), "l"(b))
#define FMA2(d,a,b,c) asm("fma.rn.f32x2 %0,%1,%2,%3;"  : "=l"(d) : "l"(a), "l"(b), "l"(c))
#define ABS_MASK 0x7FFFFFFF7FFFFFFFULL

__global__ __launch_bounds__(512) void pair_abs_kernel(
    const float* __restrict__ Aa, const float* __restrict__ Cc,
    const float* __restrict__ w2, const float* __restrict__ b2p,
    float* __restrict__ out)
{
    __shared__ float  aS[2][32][64];    // [h][i]
    __shared__ float  cD[2][32][128];   // [h][2j] duplicated (c,c)
    __shared__ float2 wD[HH];           // (w,w)
    __shared__ float  daS[64], dcS[64];

    const int tid = threadIdx.x;
    const int tx  = tid & 31;           // j-pair: j = 2tx, 2tx+1
    const int ty  = tid >> 5;           // 0..15: i = 4ty..4ty+3
    const int i0  = blockIdx.x << 6, j0 = blockIdx.y << 6;
    const int b   = blockIdx.z;
    if (tid < HH) { float w = w2[tid]; wD[tid] = make_float2(w, w); }

    // staging: 64 rows x 32 h, 4 floats per thread
    const int sRow = tid >> 3;          // 0..63
    const int sh   = (tid & 7) << 2;    // 0,4,...,28

    const float* Ab = Aa + ((size_t)b * NNODE + i0) * HH;
    const float* Cb = Cc + ((size_t)b * NNODE + j0) * HH;

    ull acc00 = 0, acc01 = 0, acc10 = 0, acc11 = 0;
    float pa_dot = 0.f, pc_dot = 0.f;

    float4 av, cv;
    auto load_regs = [&](int h0) {
        av = *reinterpret_cast<const float4*>(Ab + (size_t)sRow * HH + h0 + sh);
        cv = *reinterpret_cast<const float4*>(Cb + (size_t)sRow * HH + h0 + sh);
    };
    auto store_smem = [&](int s, int h0) {
        aS[s][sh+0][sRow]=av.x; aS[s][sh+1][sRow]=av.y;
        aS[s][sh+2][sRow]=av.z; aS[s][sh+3][sRow]=av.w;
        *reinterpret_cast<float2*>(&cD[s][sh+0][sRow<<1]) = make_float2(cv.x, cv.x);
        *reinterpret_cast<float2*>(&cD[s][sh+1][sRow<<1]) = make_float2(cv.y, cv.y);
        *reinterpret_cast<float2*>(&cD[s][sh+2][sRow<<1]) = make_float2(cv.z, cv.z);
        *reinterpret_cast<float2*>(&cD[s][sh+3][sRow<<1]) = make_float2(cv.w, cv.w);
        pa_dot += av.x*wD[h0+sh+0].x + av.y*wD[h0+sh+1].x
                + av.z*wD[h0+sh+2].x + av.w*wD[h0+sh+3].x;
        pc_dot += cv.x*wD[h0+sh+0].x + cv.y*wD[h0+sh+1].x
                + cv.z*wD[h0+sh+2].x + cv.w*wD[h0+sh+3].x;
    };

    load_regs(0);
    __syncthreads();            // wD visible before fused dots use it
    store_smem(0, 0);
    __syncthreads();

    int cur = 0;
    for (int t = 1; t <= 8; ++t) {
        const bool hn = (t < 8);
        if (hn) load_regs(t << 5);
        #pragma unroll
        for (int h = 0; h < 32; ++h) {
            ulonglong2 pa = *reinterpret_cast<const ulonglong2*>(&aS[cur][h][ty << 2]);
            ulonglong2 pc = *reinterpret_cast<const ulonglong2*>(&cD[cur][h][tx << 2]);
            ull wv = *reinterpret_cast<const ull*>(&wD[((t - 1) << 5) + h]);
            ull s0;
            ADD2(s0, pa.x, pc.x); s0 &= ABS_MASK; FMA2(acc00, s0, wv, acc00);
            ADD2(s0, pa.x, pc.y); s0 &= ABS_MASK; FMA2(acc01, s0, wv, acc01);
            ADD2(s0, pa.y, pc.x); s0 &= ABS_MASK; FMA2(acc10, s0, wv, acc10);
            ADD2(s0, pa.y, pc.y); s0 &= ABS_MASK; FMA2(acc11, s0, wv, acc11);
        }
        if (hn) {
            const int nxt = cur ^ 1;
            store_smem(nxt, t << 5);
            __syncthreads();
            cur = nxt;
        }
    }

    // reduce fused dots over the 8 lanes sharing sRow (tid&7 group)
    {
        float v = pa_dot, u = pc_dot;
        v += __shfl_xor_sync(0xffffffffu, v, 1);
        v += __shfl_xor_sync(0xffffffffu, v, 2);
        v += __shfl_xor_sync(0xffffffffu, v, 4);
        u += __shfl_xor_sync(0xffffffffu, u, 1);
        u += __shfl_xor_sync(0xffffffffu, u, 2);
        u += __shfl_xor_sync(0xffffffffu, u, 4);
        if ((tid & 7) == 0) { daS[sRow] = v; dcS[sRow] = u; }
    }
    __syncthreads();

    const float b2v = b2p[0];
    const int jcol = j0 + (tx << 1);
    const float dc0 = dcS[(tx << 1) + 0];
    const float dc1 = dcS[(tx << 1) + 1];
    // acc00: i-pair (4ty,4ty+1) @ j=2tx ; acc01: same pair @ j=2tx+1
    // acc10: i-pair (4ty+2,4ty+3) @ j=2tx ; acc11: @ j=2tx+1
    float rA0 = __uint_as_float((u32)(acc00 & 0xffffffffu));
    float rA1 = __uint_as_float((u32)(acc00 >> 32));
    float rB0 = __uint_as_float((u32)(acc01 & 0xffffffffu));
    float rB1 = __uint_as_float((u32)(acc01 >> 32));
    float rC0 = __uint_as_float((u32)(acc10 & 0xffffffffu));
    float rC1 = __uint_as_float((u32)(acc10 >> 32));
    float rD0 = __uint_as_float((u32)(acc11 & 0xffffffffu));
    float rD1 = __uint_as_float((u32)(acc11 >> 32));
    #pragma unroll
    for (int di = 0; di < 4; ++di) {
        const int i = (ty << 2) + di;
        const float dai = daS[i];
        float rj0, rj1;
        if (di == 0)      { rj0 = rA0; rj1 = rB0; }
        else if (di == 1) { rj0 = rA1; rj1 = rB1; }
        else if (di == 2) { rj0 = rC0; rj1 = rD0; }
        else              { rj0 = rC1; rj1 = rD1; }
        float2 o;
        o.x = 1.f / (1.f + __expf(-(0.5f * (dai + dc0 + rj0) + b2v)));
        o.y = 1.f / (1.f + __expf(-(0.5f * (dai + dc1 + rj1) + b2v)));
        *reinterpret_cast<float2*>(out + ((size_t)b * NNODE + i0 + i) * NNODE + jcol) = o;
    }
}

// ---------------- fused invariance reduction (single launch) ----------------
__global__ __launch_bounds__(256) void reduce_all(
    const float* __restrict__ causal, float* __restrict__ inv)
{
    const int p = blockIdx.x * 256 + threadIdx.x;
    float x[8];
    #pragma unroll
    for (int b = 0; b < 8; ++b) x[b] = causal[b * NMAT + p];
    float stab = 0.f, s = 0.f;
    #pragma unroll
    for (int b = 0; b < 8; ++b) { stab += fabsf(x[b] - x[(b + 7) & 7]); s += x[b]; }
    const float m = s * 0.125f;
    float var = 0.f;
    #pragma unroll
    for (int b = 0; b < 8; ++b) { float d = x[b] - m; var = fmaf(d, d, var); }
    float sd = sqrtf(var * (1.f / 7.f));

    #pragma unroll
    for (int o = 16; o; o >>= 1) {
        stab += __shfl_down_sync(0xffffffffu, stab, o);
        sd   += __shfl_down_sync(0xffffffffu, sd, o);
    }
    __shared__ float sm[8][2];
    const int wid = threadIdx.x >> 5, lane = threadIdx.x & 31;
    if (lane == 0) { sm[wid][0] = stab; sm[wid][1] = sd; }
    __syncthreads();
    if (threadIdx.x == 0) {
        float a = 0.f, c = 0.f;
        #pragma unroll
        for (int w = 0; w < 8; ++w) { a += sm[w][0]; c += sm[w][1]; }
        g_partial[blockIdx.x * 2 + 0] = a;
        g_partial[blockIdx.x * 2 + 1] = c;
    }

    __shared__ int isLast;
    __threadfence();
    if (threadIdx.x == 0) {
        u32 cdone = atomicAdd(&g_cnt, 1u);
        isLast = (cdone == 255u) ? 1 : 0;
    }
    __syncthreads();
    if (isLast) {
        float a = g_partial[threadIdx.x * 2 + 0];
        float c = g_partial[threadIdx.x * 2 + 1];
        #pragma unroll
        for (int o = 16; o; o >>= 1) {
            a += __shfl_down_sync(0xffffffffu, a, o);
            c += __shfl_down_sync(0xffffffffu, c, o);
        }
        if (lane == 0) { sm[wid][0] = a; sm[wid][1] = c; }
        __syncthreads();
        if (threadIdx.x == 0) {
            float sa = 0.f, sc = 0.f;
            #pragma unroll
            for (int w = 0; w < 8; ++w) { sa += sm[w][0]; sc += sm[w][1]; }
            const float stability   = sa / (8.f * 65536.f);
            const float consistency = sc / 65536.f;
            inv[0] = 1.f - (stability + consistency) * 0.5f;
            g_cnt = 0u;
        }
    }
}

// ---------------- launch ----------------
extern "C" void kernel_launch(void* const* d_in, const int* in_sizes, int n_in,
                              void* d_out, int out_size)
{
    const float* img    = (const float*)d_in[0];
    const float* txt    = (const float*)d_in[1];
    const float* ft_W1  = (const float*)d_in[2];
    const float* ft_b1  = (const float*)d_in[3];
    const float* ft_W2  = (const float*)d_in[4];
    const float* ft_b2  = (const float*)d_in[5];
    const float* sl_W1a = (const float*)d_in[6];
    const float* sl_W1b = (const float*)d_in[7];
    const float* sl_b1  = (const float*)d_in[8];
    const float* sl_W2  = (const float*)d_in[9];
    const float* sl_b2  = (const float*)d_in[10];
    const float* cn_W1a = (const float*)d_in[11];
    const float* cn_W1b = (const float*)d_in[12];
    const float* cn_b1  = (const float*)d_in[13];
    const float* cn_W2  = (const float*)d_in[14];
    const float* cn_b2  = (const float*)d_in[15];

    float* outp      = (float*)d_out;
    float* structure = outp;
    float* causal    = outp + OUT_MAT;
    float* inv       = outp + 2 * OUT_MAT;

    float *x1, *h, *ac;
    cudaGetSymbolAddress((void**)&x1, g_x1);
    cudaGetSymbolAddress((void**)&h,  g_h);
    cudaGetSymbolAddress((void**)&ac, g_ac);

    const dim3 gemm_grid(M2 / 128, HH / 64);            // 32 x 4 = 128 blocks
    const dim3 pair_grid(NNODE / 64, NNODE / 64, BB);   // 4 x 4 x 8 = 128 blocks

    gemm2_bf16<<<gemm_grid, 256>>>(img, txt, ft_W1, ft_W1, ft_b1, ft_b1, x1, FF, 1);
    gemm2_bf16<<<gemm_grid, 256>>>(x1, x1 + (size_t)MM * HH, ft_W2, ft_W2, ft_b2, ft_b2, h, HH, 0);
    gemm2_bf16<<<gemm_grid, 256>>>(h, h + (size_t)MM * HH, sl_W1a, sl_W1b, sl_b1, nullptr, ac, HH, 0);
    pair_abs_kernel<<<pair_grid, 512>>>(ac, ac + (size_t)MM * HH, sl_W2, sl_b2, structure);
    gemm2_bf16<<<gemm_grid, 256>>>(structure, structure, cn_W1a, cn_W1b, cn_b1, nullptr, ac, HH, 0);
    pair_abs_kernel<<<pair_grid, 512>>>(ac, ac + (size_t)MM * HH, cn_W2, cn_b2, causal);
    reduce_all<<<256, 256>>>(causal, inv);
}